// round 12
// baseline (speedup 1.0000x reference)
#include <cuda_runtime.h>
#include <cuda_bf16.h>
#include <cstdint>
#include <cstddef>

// ---------------------------------------------------------------------------
// Problem constants
// ---------------------------------------------------------------------------
#define NPAPER  100000
#define NAUTHOR 50000
#define NEDGE   600000
#define HD      128
#define IMG     16384          // elements per weight image (128x128)
#define ROWP    72             // padded row stride (bf16 elems) in smem tiles

typedef unsigned short ushortT;

// ---------------------------------------------------------------------------
// Static scratch — all activations live as pre-split bf16 hi/lo pairs
// ---------------------------------------------------------------------------
__device__ ushortT g_xph[(size_t)NPAPER * 256];
__device__ ushortT g_xpl[(size_t)NPAPER * 256];
__device__ ushortT g_xah[(size_t)NAUTHOR * 128];
__device__ ushortT g_xal[(size_t)NAUTHOR * 128];
__device__ ushortT g_yph0[(size_t)NPAPER * HD];
__device__ ushortT g_ypl0[(size_t)NPAPER * HD];
__device__ ushortT g_yph1[(size_t)NPAPER * HD];
__device__ ushortT g_ypl1[(size_t)NPAPER * HD];
__device__ ushortT g_yah0[(size_t)NAUTHOR * HD];
__device__ ushortT g_yal0[(size_t)NAUTHOR * HD];
__device__ ushortT g_yah1[(size_t)NAUTHOR * HD];
__device__ ushortT g_yal1[(size_t)NAUTHOR * HD];
__device__ ushortT g_mp1h[(size_t)NPAPER * HD];
__device__ ushortT g_mp1l[(size_t)NPAPER * HD];
__device__ ushortT g_mp2h[(size_t)NPAPER * HD];
__device__ ushortT g_mp2l[(size_t)NPAPER * HD];
__device__ ushortT g_mah[(size_t)NAUTHOR * HD];
__device__ ushortT g_mal[(size_t)NAUTHOR * HD];

__device__ int g_rp_a2p[NPAPER + 1];
__device__ int g_rp_p2a[NAUTHOR + 1];
__device__ int g_rp_p2p[NPAPER + 1];
__device__ int g_col_a2p[NEDGE];
__device__ int g_col_p2a[NEDGE];
__device__ int g_col_p2p[NEDGE];
__device__ int g_cnt[NPAPER + 1];
__device__ int g_bsums[1024];

// Pre-split bf16 weight images, transposed to [n][k] (14 images)
__device__ ushortT g_wih[14 * IMG];
__device__ ushortT g_wil[14 * IMG];

// ---------------------------------------------------------------------------
// helpers
// ---------------------------------------------------------------------------
__device__ __forceinline__ uint32_t smem_u32(const void* p) {
    uint32_t a;
    asm("{ .reg .u64 t; cvta.to.shared.u64 t, %1; cvt.u32.u64 %0, t; }" : "=r"(a) : "l"(p));
    return a;
}
__device__ __forceinline__ void splitbf(float f, ushortT& h, float& lo) {
    __nv_bfloat16 b = __float2bfloat16(f);
    h = __bfloat16_as_ushort(b);
    lo = f - __bfloat162float(b);
}
__device__ __forceinline__ ushortT bf16of(float f) {
    __nv_bfloat16 b = __float2bfloat16(f);
    return __bfloat16_as_ushort(b);
}
__device__ __forceinline__ float2 bfp2f(uint32_t p) {
    __nv_bfloat162 b = *reinterpret_cast<__nv_bfloat162*>(&p);
    return __bfloat1622float2(b);
}

// mma.sync m16n8k16 row.col f32.bf16.bf16.f32  (baseline sm_80+)
__device__ __forceinline__ void mma16816(float* c, const uint32_t* a, const uint32_t* b) {
    asm volatile(
        "mma.sync.aligned.m16n8k16.row.col.f32.bf16.bf16.f32 "
        "{%0,%1,%2,%3}, {%4,%5,%6,%7}, {%8,%9}, {%0,%1,%2,%3};"
        : "+f"(c[0]), "+f"(c[1]), "+f"(c[2]), "+f"(c[3])
        : "r"(a[0]), "r"(a[1]), "r"(a[2]), "r"(a[3]), "r"(b[0]), "r"(b[1]));
}
// ldmatrix x4 (baseline sm_75+)
__device__ __forceinline__ void ldm_x4(uint32_t* r, uint32_t addr) {
    asm volatile("ldmatrix.sync.aligned.m8n8.x4.shared.b16 {%0,%1,%2,%3}, [%4];"
                 : "=r"(r[0]), "=r"(r[1]), "=r"(r[2]), "=r"(r[3]) : "r"(addr));
}
// cp.async 16B (baseline sm_80+)
__device__ __forceinline__ void cp16(uint32_t dst, const void* src) {
    asm volatile("cp.async.cg.shared.global [%0], [%1], 16;" :: "r"(dst), "l"(src));
}
#define CP_COMMIT() asm volatile("cp.async.commit_group;" ::: "memory")
#define CP_WAIT1()  asm volatile("cp.async.wait_group 1;"  ::: "memory")

__device__ __forceinline__ void store_split2(ushortT* Yh, ushortT* Yl, size_t idx, float2 o) {
    __nv_bfloat16 hx = __float2bfloat16(o.x), hy = __float2bfloat16(o.y);
    float lx = o.x - __bfloat162float(hx);
    float ly = o.y - __bfloat162float(hy);
    ushort2 hv, lv;
    hv.x = __bfloat16_as_ushort(hx); hv.y = __bfloat16_as_ushort(hy);
    lv.x = bf16of(lx); lv.y = bf16of(ly);
    *(ushort2*)(Yh + idx) = hv;
    *(ushort2*)(Yl + idx) = lv;
}

// ---------------------------------------------------------------------------
// Weight prep: split W into bf16 hi/lo, transposed to [n][k].
// ---------------------------------------------------------------------------
__global__ void prep_w_kernel(const float* __restrict__ lin_p_w, const float* __restrict__ lin_a_w,
                              const float* __restrict__ Wl, const float* __restrict__ Wr,
                              const float* __restrict__ lin_w,
                              ushortT* __restrict__ ih, ushortT* __restrict__ il) {
    int img = blockIdx.x;
    int N = (img == 13) ? 64 : 128;
    int total = N * 128;
    for (int i = threadIdx.x; i < total; i += blockDim.x) {
        int n = i / 128, k = i % 128;
        float w;
        if (img == 0)       w = lin_p_w[k * 128 + n];
        else if (img == 1)  w = lin_p_w[(k + 128) * 128 + n];
        else if (img == 2)  w = lin_a_w[k * 128 + n];
        else if (img <= 8)  w = Wl[(size_t)(img - 3) * IMG + k * 128 + n];
        else if (img <= 10) {
            int l = img - 9;
            w = Wr[(size_t)(l * 3 + 0) * IMG + k * 128 + n] +
                Wr[(size_t)(l * 3 + 2) * IMG + k * 128 + n];
        }
        else if (img <= 12) w = Wr[(size_t)((img - 11) * 3 + 1) * IMG + k * 128 + n];
        else                w = lin_w[k * 64 + n];
        ushortT h; float lo;
        splitbf(w, h, lo);
        size_t base = (size_t)img * IMG + (size_t)n * 128 + k;
        ih[base] = h;
        il[base] = bf16of(lo);
    }
}

// ---------------------------------------------------------------------------
// Input-feature split: x_paper/x_author -> bf16 hi/lo
// ---------------------------------------------------------------------------
__global__ void prep_x_kernel(const float* __restrict__ xp, const float* __restrict__ xa,
                              ushortT* __restrict__ xph, ushortT* __restrict__ xpl,
                              ushortT* __restrict__ xah, ushortT* __restrict__ xal) {
    const int NP_E = NPAPER * 256;
    const int NA_E = NAUTHOR * 128;
    int stride = gridDim.x * blockDim.x;
    for (int i = blockIdx.x * blockDim.x + threadIdx.x; i < NP_E + NA_E; i += stride) {
        if (i < NP_E) {
            ushortT h; float lo;
            splitbf(xp[i], h, lo);
            xph[i] = h; xpl[i] = bf16of(lo);
        } else {
            int j = i - NP_E;
            ushortT h; float lo;
            splitbf(xa[j], h, lo);
            xah[j] = h; xal[j] = bf16of(lo);
        }
    }
}

// ---------------------------------------------------------------------------
// Pipelined split-bf16 tensor-core GEMM.  CTA = 512 threads, tile 128 x N.
// 16 warps (4 m x 4 n).  3-buffer cp.async pipeline over 64-k chunks:
// one barrier per chunk, copies of chunks c+1 and c+2 in flight during mma c.
// ---------------------------------------------------------------------------
template<int N>
__global__ void __launch_bounds__(512, 1)
gemm_bf(const ushortT* Ah0, const ushortT* Al0, int lda0, int ko0,
        const ushortT* Wh0, const ushortT* Wl0,
        const ushortT* Ah1, const ushortT* Al1, int lda1, int ko1,
        const ushortT* Wh1, const ushortT* Wl1,
        const ushortT* Ah2, const ushortT* Al2, int lda2, int ko2,
        const ushortT* Wh2, const ushortT* Wl2,
        int nStages, int M, const float* b0, const float* b1,
        float* Yf, ushortT* Yh, ushortT* Yl, int relu) {
    extern __shared__ char smem[];
    constexpr int NT = N / 32;              // 8-col n-tiles per warp (4 or 2)
    constexpr int A_BYTES = 128 * ROWP * 2; // 18432
    constexpr int W_BYTES = N * ROWP * 2;
    constexpr int BUF = 2 * A_BYTES + 2 * W_BYTES;

    int tid = threadIdx.x, wid = tid >> 5, lane = tid & 31;
    int g = lane >> 2, t4 = lane & 3;
    int warp_m = wid & 3, warp_n = wid >> 2;
    int rowBase = blockIdx.x * 128;
    uint32_t sb = smem_u32(smem);

    const ushortT* Ahs[3] = {Ah0, Ah1, Ah2};
    const ushortT* Als[3] = {Al0, Al1, Al2};
    const ushortT* Whs[3] = {Wh0, Wh1, Wh2};
    const ushortT* Wls[3] = {Wl0, Wl1, Wl2};
    const int ldas[3] = {lda0, lda1, lda2};
    const int kos[3] = {ko0, ko1, ko2};

    // ldmatrix per-thread base offsets (within a buffer)
    uint32_t a_off = (uint32_t)((warp_m * 32 + (lane & 15)) * ROWP + ((lane >> 4) << 3)) * 2;
    uint32_t b_off = (uint32_t)((warp_n * (N / 4) + (lane & 7) + ((lane >> 4) << 3)) * ROWP
                                + (((lane >> 3) & 1) << 3)) * 2;

    auto issue = [&](int c, int buf) {
        int stage = c >> 1, half = c & 1;
        const ushortT* Ah = Ahs[stage];
        const ushortT* Al = Als[stage];
        const ushortT* Wh = Whs[stage];
        const ushortT* Wl = Wls[stage];
        int lda = ldas[stage];
        int koff = kos[stage] + half * 64;
        int kc = half * 64;
        uint32_t base = sb + (uint32_t)buf * BUF;
        const int total = (256 + 2 * N) * 8;
        for (int i = tid; i < total; i += 512) {
            int row = i >> 3, seg = i & 7;
            if (row < 128) {
                int grow = rowBase + row; if (grow > M - 1) grow = M - 1;
                cp16(base + row * 144 + seg * 16, Ah + (size_t)grow * lda + koff + seg * 8);
            } else if (row < 256) {
                int r = row - 128;
                int grow = rowBase + r; if (grow > M - 1) grow = M - 1;
                cp16(base + A_BYTES + r * 144 + seg * 16, Al + (size_t)grow * lda + koff + seg * 8);
            } else if (row < 256 + N) {
                int n = row - 256;
                cp16(base + 2 * A_BYTES + n * 144 + seg * 16, Wh + (size_t)n * 128 + kc + seg * 8);
            } else {
                int n = row - 256 - N;
                cp16(base + 2 * A_BYTES + W_BYTES + n * 144 + seg * 16,
                     Wl + (size_t)n * 128 + kc + seg * 8);
            }
        }
    };

    float acc[2][NT][4];
#pragma unroll
    for (int m = 0; m < 2; m++)
#pragma unroll
        for (int n = 0; n < NT; n++)
#pragma unroll
            for (int q = 0; q < 4; q++) acc[m][n][q] = 0.f;

    int nChunks = nStages * 2;
    issue(0, 0); CP_COMMIT();
    if (nChunks > 1) issue(1, 1);
    CP_COMMIT();

    int bufc = 0;
    for (int c = 0; c < nChunks; c++) {
        CP_WAIT1();               // chunk c complete (only c+1's group may remain)
        __syncthreads();          // all warps done reading buffer (c-1)%3
        int nb = bufc + 2; if (nb >= 3) nb -= 3;
        if (c + 2 < nChunks) issue(c + 2, nb);   // writes (c+2)%3 == (c-1)%3: safe
        CP_COMMIT();              // empty group at tail keeps counts aligned
        uint32_t bb = sb + (uint32_t)bufc * BUF;
        uint32_t aH = bb + a_off, aL = aH + A_BYTES;
        uint32_t wH = bb + 2 * A_BYTES + b_off, wL = wH + W_BYTES;
#pragma unroll
        for (int k16 = 0; k16 < 64; k16 += 16) {
            uint32_t ah[2][4], al[2][4];
#pragma unroll
            for (int mt = 0; mt < 2; mt++) {
                uint32_t d = (uint32_t)(mt * 16 * ROWP + k16) * 2;
                ldm_x4(ah[mt], aH + d);
                ldm_x4(al[mt], aL + d);
            }
#pragma unroll
            for (int ntp = 0; ntp < NT / 2; ntp++) {
                uint32_t d = (uint32_t)(ntp * 16 * ROWP + k16) * 2;
                uint32_t bh[4], blo[4];
                ldm_x4(bh, wH + d);
                ldm_x4(blo, wL + d);
#pragma unroll
                for (int h2 = 0; h2 < 2; h2++) {
                    int nt = ntp * 2 + h2;
#pragma unroll
                    for (int mt = 0; mt < 2; mt++) {
                        mma16816(acc[mt][nt], ah[mt], bh + h2 * 2);
                        mma16816(acc[mt][nt], ah[mt], blo + h2 * 2);
                        mma16816(acc[mt][nt], al[mt], bh + h2 * 2);
                    }
                }
            }
        }
        bufc = (bufc + 1 == 3) ? 0 : bufc + 1;
    }

    // --- epilogue: hi/lo bf16 always; f32 optional (classifier) ---
#pragma unroll
    for (int mt = 0; mt < 2; mt++) {
        int r0 = rowBase + warp_m * 32 + mt * 16 + g;
        int r1 = r0 + 8;
#pragma unroll
        for (int nt = 0; nt < NT; nt++) {
            int col = warp_n * (N / 4) + nt * 8 + t4 * 2;
            float bx = b0[col], by = b0[col + 1];
            if (b1) { bx += b1[col]; by += b1[col + 1]; }
            float2 o0, o1;
            o0.x = acc[mt][nt][0] + bx; o0.y = acc[mt][nt][1] + by;
            o1.x = acc[mt][nt][2] + bx; o1.y = acc[mt][nt][3] + by;
            if (relu) {
                o0.x = fmaxf(o0.x, 0.f); o0.y = fmaxf(o0.y, 0.f);
                o1.x = fmaxf(o1.x, 0.f); o1.y = fmaxf(o1.y, 0.f);
            }
            if (r0 < M) {
                if (Yf) *(float2*)(Yf + (size_t)r0 * N + col) = o0;
                if (Yh) store_split2(Yh, Yl, (size_t)r0 * N + col, o0);
            }
            if (r1 < M) {
                if (Yf) *(float2*)(Yf + (size_t)r1 * N + col) = o1;
                if (Yh) store_split2(Yh, Yl, (size_t)r1 * N + col, o1);
            }
        }
    }
}

// ---------------------------------------------------------------------------
// CSR build kernels
// ---------------------------------------------------------------------------
__global__ void zero_int_kernel(int* __restrict__ p, int n) {
    int stride = gridDim.x * blockDim.x;
    for (int i = blockIdx.x * blockDim.x + threadIdx.x; i < n; i += stride) p[i] = 0;
}
__global__ void hist_kernel(const int* __restrict__ dst, int* __restrict__ cnt, int n) {
    int i = blockIdx.x * blockDim.x + threadIdx.x;
    if (i < n) atomicAdd(&cnt[dst[i]], 1);
}
__global__ void scan_block_kernel(const int* __restrict__ in, int* __restrict__ out,
                                  int* __restrict__ bsums, int n) {
    __shared__ int sh[1024];
    int gid = blockIdx.x * 1024 + threadIdx.x;
    int v = (gid < n) ? in[gid] : 0;
    sh[threadIdx.x] = v;
    __syncthreads();
    for (int off = 1; off < 1024; off <<= 1) {
        int t = (threadIdx.x >= off) ? sh[threadIdx.x - off] : 0;
        __syncthreads();
        sh[threadIdx.x] += t;
        __syncthreads();
    }
    if (gid < n) out[gid] = sh[threadIdx.x] - v;
    if (threadIdx.x == 1023) bsums[blockIdx.x] = sh[1023];
}
__global__ void scan_partials_kernel(int* __restrict__ bsums, int nb) {
    __shared__ int sh[1024];
    int v = (threadIdx.x < nb) ? bsums[threadIdx.x] : 0;
    sh[threadIdx.x] = v;
    __syncthreads();
    for (int off = 1; off < 1024; off <<= 1) {
        int t = (threadIdx.x >= off) ? sh[threadIdx.x - off] : 0;
        __syncthreads();
        sh[threadIdx.x] += t;
        __syncthreads();
    }
    if (threadIdx.x < nb) bsums[threadIdx.x] = sh[threadIdx.x] - v;
}
__global__ void scan_add_kernel(int* __restrict__ rowptr, int* __restrict__ cnt,
                                const int* __restrict__ bsums, int n, int E) {
    int gid = blockIdx.x * 1024 + threadIdx.x;
    if (gid < n) {
        int r = rowptr[gid] + bsums[blockIdx.x];
        rowptr[gid] = r;
        cnt[gid] = r;
    }
    if (gid == 0) rowptr[n] = E;
}
__global__ void fill_csr_kernel(const int* __restrict__ src, const int* __restrict__ dst,
                                int* __restrict__ cnt, int* __restrict__ col, int n) {
    int i = blockIdx.x * blockDim.x + threadIdx.x;
    if (i < n) {
        int p = atomicAdd(&cnt[dst[i]], 1);
        col[p] = src[i];
    }
}

// ---------------------------------------------------------------------------
// Fused 3-way gather-mean: consumes hi/lo bf16 features, emits hi/lo bf16.
// ---------------------------------------------------------------------------
__device__ __forceinline__ void gather_one(const uint2* __restrict__ fH,
                                           const uint2* __restrict__ fL,
                                           const int* __restrict__ rowptr,
                                           const int* __restrict__ col,
                                           uint2* __restrict__ outH, uint2* __restrict__ outL,
                                           int node, int lane) {
    int e0 = __ldg(&rowptr[node]);
    int e1 = __ldg(&rowptr[node + 1]);
    float4 a0 = make_float4(0.f, 0.f, 0.f, 0.f);
    float4 a1 = make_float4(0.f, 0.f, 0.f, 0.f);
    int e = e0;
    for (; e + 1 < e1; e += 2) {
        int s0 = __ldg(&col[e]);
        int s1 = __ldg(&col[e + 1]);
        uint2 h0 = fH[(size_t)s0 * 32 + lane];
        uint2 l0 = fL[(size_t)s0 * 32 + lane];
        uint2 h1 = fH[(size_t)s1 * 32 + lane];
        uint2 l1 = fL[(size_t)s1 * 32 + lane];
        float2 p0 = bfp2f(h0.x), p1 = bfp2f(h0.y), q0 = bfp2f(l0.x), q1 = bfp2f(l0.y);
        float2 r0 = bfp2f(h1.x), r1 = bfp2f(h1.y), s0f = bfp2f(l1.x), s1f = bfp2f(l1.y);
        a0.x += p0.x + q0.x; a0.y += p0.y + q0.y;
        a0.z += p1.x + q1.x; a0.w += p1.y + q1.y;
        a1.x += r0.x + s0f.x; a1.y += r0.y + s0f.y;
        a1.z += r1.x + s1f.x; a1.w += r1.y + s1f.y;
    }
    if (e < e1) {
        int s = __ldg(&col[e]);
        uint2 h = fH[(size_t)s * 32 + lane];
        uint2 l = fL[(size_t)s * 32 + lane];
        float2 p0 = bfp2f(h.x), p1 = bfp2f(h.y), q0 = bfp2f(l.x), q1 = bfp2f(l.y);
        a0.x += p0.x + q0.x; a0.y += p0.y + q0.y;
        a0.z += p1.x + q1.x; a0.w += p1.y + q1.y;
    }
    float inv = 1.0f / fmaxf((float)(e1 - e0), 1.0f);
    float o[4];
    o[0] = (a0.x + a1.x) * inv; o[1] = (a0.y + a1.y) * inv;
    o[2] = (a0.z + a1.z) * inv; o[3] = (a0.w + a1.w) * inv;
    ushortT h[4], lw[4];
    float lo;
#pragma unroll
    for (int q = 0; q < 4; q++) { splitbf(o[q], h[q], lo); lw[q] = bf16of(lo); }
    uint2 hv, lv;
    hv.x = (uint32_t)h[0] | ((uint32_t)h[1] << 16);
    hv.y = (uint32_t)h[2] | ((uint32_t)h[3] << 16);
    lv.x = (uint32_t)lw[0] | ((uint32_t)lw[1] << 16);
    lv.y = (uint32_t)lw[2] | ((uint32_t)lw[3] << 16);
    outH[(size_t)node * 32 + lane] = hv;
    outL[(size_t)node * 32 + lane] = lv;
}

__global__ void gather3_kernel(const uint2* __restrict__ fAh, const uint2* __restrict__ fAl,
                               const uint2* __restrict__ fPh, const uint2* __restrict__ fPl,
                               const int* __restrict__ rp1, const int* __restrict__ c1,
                               uint2* __restrict__ mp1h, uint2* __restrict__ mp1l,
                               const int* __restrict__ rp3, const int* __restrict__ c3,
                               uint2* __restrict__ mp2h, uint2* __restrict__ mp2l,
                               const int* __restrict__ rp2, const int* __restrict__ c2,
                               uint2* __restrict__ mah, uint2* __restrict__ mal) {
    int w = (blockIdx.x * blockDim.x + threadIdx.x) >> 5;
    int lane = threadIdx.x & 31;
    if (w < NPAPER) {
        gather_one(fAh, fAl, rp1, c1, mp1h, mp1l, w, lane);
    } else if (w < 2 * NPAPER) {
        gather_one(fPh, fPl, rp3, c3, mp2h, mp2l, w - NPAPER, lane);
    } else if (w < 2 * NPAPER + NAUTHOR) {
        gather_one(fPh, fPl, rp2, c2, mah, mal, w - 2 * NPAPER, lane);
    }
}

// ---------------------------------------------------------------------------
// Host helpers
// ---------------------------------------------------------------------------
static void build_csr(const int* src, const int* dst, int ndst,
                      int* rowptr, int* col, int* cnt, int* bsums) {
    int nb = (ndst + 1023) / 1024;
    zero_int_kernel<<<256, 256>>>(cnt, ndst);
    hist_kernel<<<(NEDGE + 255) / 256, 256>>>(dst, cnt, NEDGE);
    scan_block_kernel<<<nb, 1024>>>(cnt, rowptr, bsums, ndst);
    scan_partials_kernel<<<1, 1024>>>(bsums, nb);
    scan_add_kernel<<<nb, 1024>>>(rowptr, cnt, bsums, ndst, NEDGE);
    fill_csr_kernel<<<(NEDGE + 255) / 256, 256>>>(src, dst, cnt, col, NEDGE);
}

extern "C" void kernel_launch(void* const* d_in, const int* in_sizes, int n_in,
                              void* d_out, int out_size) {
    const float* x_paper  = (const float*)d_in[0];
    const float* x_author = (const float*)d_in[1];
    const float* lin_p_w  = (const float*)d_in[2];
    const float* lin_p_b  = (const float*)d_in[3];
    const float* lin_a_w  = (const float*)d_in[4];
    const float* lin_a_b  = (const float*)d_in[5];
    const float* Wl       = (const float*)d_in[6];
    const float* bl       = (const float*)d_in[7];
    const float* Wr       = (const float*)d_in[8];
    const float* lin_w    = (const float*)d_in[9];
    const float* lin_b    = (const float*)d_in[10];
    const int* a2p_src = (const int*)d_in[11];
    const int* a2p_dst = (const int*)d_in[12];
    const int* p2a_src = (const int*)d_in[13];
    const int* p2a_dst = (const int*)d_in[14];
    const int* p2p_src = (const int*)d_in[15];
    const int* p2p_dst = (const int*)d_in[16];
    float* out = (float*)d_out;

    int *rp1, *rp2, *rp3, *c1, *c2, *c3, *cnt, *bsums;
    ushortT *wih, *wil, *xph, *xpl, *xah, *xal;
    ushortT *yph0, *ypl0, *yph1, *ypl1, *yah0, *yal0, *yah1, *yal1;
    ushortT *mp1h, *mp1l, *mp2h, *mp2l, *mah, *mal;
    cudaGetSymbolAddress((void**)&rp1, g_rp_a2p);
    cudaGetSymbolAddress((void**)&rp2, g_rp_p2a);
    cudaGetSymbolAddress((void**)&rp3, g_rp_p2p);
    cudaGetSymbolAddress((void**)&c1,  g_col_a2p);
    cudaGetSymbolAddress((void**)&c2,  g_col_p2a);
    cudaGetSymbolAddress((void**)&c3,  g_col_p2p);
    cudaGetSymbolAddress((void**)&cnt, g_cnt);
    cudaGetSymbolAddress((void**)&bsums, g_bsums);
    cudaGetSymbolAddress((void**)&wih, g_wih);
    cudaGetSymbolAddress((void**)&wil, g_wil);
    cudaGetSymbolAddress((void**)&xph, g_xph);
    cudaGetSymbolAddress((void**)&xpl, g_xpl);
    cudaGetSymbolAddress((void**)&xah, g_xah);
    cudaGetSymbolAddress((void**)&xal, g_xal);
    cudaGetSymbolAddress((void**)&yph0, g_yph0);
    cudaGetSymbolAddress((void**)&ypl0, g_ypl0);
    cudaGetSymbolAddress((void**)&yph1, g_yph1);
    cudaGetSymbolAddress((void**)&ypl1, g_ypl1);
    cudaGetSymbolAddress((void**)&yah0, g_yah0);
    cudaGetSymbolAddress((void**)&yal0, g_yal0);
    cudaGetSymbolAddress((void**)&yah1, g_yah1);
    cudaGetSymbolAddress((void**)&yal1, g_yal1);
    cudaGetSymbolAddress((void**)&mp1h, g_mp1h);
    cudaGetSymbolAddress((void**)&mp1l, g_mp1l);
    cudaGetSymbolAddress((void**)&mp2h, g_mp2h);
    cudaGetSymbolAddress((void**)&mp2l, g_mp2l);
    cudaGetSymbolAddress((void**)&mah, g_mah);
    cudaGetSymbolAddress((void**)&mal, g_mal);

    const int BUF128 = 2 * 128 * ROWP * 2 + 2 * 128 * ROWP * 2;  // 73728
    const int BUF64  = 2 * 128 * ROWP * 2 + 2 * 64 * ROWP * 2;   // 55296
    const int S128 = 3 * BUF128;  // 221184
    const int S64  = 3 * BUF64;   // 165888
    cudaFuncSetAttribute(gemm_bf<128>, cudaFuncAttributeMaxDynamicSharedMemorySize, S128);
    cudaFuncSetAttribute(gemm_bf<64>,  cudaFuncAttributeMaxDynamicSharedMemorySize, S64);

    const int GP = (NPAPER + 127) / 128;   // 782
    const int GA = (NAUTHOR + 127) / 128;  // 391

    // 1: weight prep
    prep_w_kernel<<<14, 256>>>(lin_p_w, lin_a_w, Wl, Wr, lin_w, wih, wil);
    // 2: input split
    prep_x_kernel<<<4096, 256>>>(x_paper, x_author, xph, xpl, xah, xal);
    // 3: first CSR zero
    zero_int_kernel<<<256, 256>>>(cnt, NPAPER);
    // 4: paper projection (K=256 -> 2 stages), relu  [ncu capture slot]
    gemm_bf<128><<<GP, 512, S128>>>(
        xph, xpl, 256, 0,   wih + 0 * IMG, wil + 0 * IMG,
        xph, xpl, 256, 128, wih + 1 * IMG, wil + 1 * IMG,
        nullptr, nullptr, 0, 0, nullptr, nullptr,
        2, NPAPER, lin_p_b, nullptr, nullptr, yph0, ypl0, 1);
    // 5: author projection, relu
    gemm_bf<128><<<GA, 512, S128>>>(
        xah, xal, 128, 0, wih + 2 * IMG, wil + 2 * IMG,
        nullptr, nullptr, 0, 0, nullptr, nullptr,
        nullptr, nullptr, 0, 0, nullptr, nullptr,
        1, NAUTHOR, lin_a_b, nullptr, nullptr, yah0, yal0, 1);

    // finish CSR a2p (cnt already zeroed)
    {
        int nb = (NPAPER + 1023) / 1024;
        hist_kernel<<<(NEDGE + 255) / 256, 256>>>(a2p_dst, cnt, NEDGE);
        scan_block_kernel<<<nb, 1024>>>(cnt, rp1, bsums, NPAPER);
        scan_partials_kernel<<<1, 1024>>>(bsums, nb);
        scan_add_kernel<<<nb, 1024>>>(rp1, cnt, bsums, NPAPER, NEDGE);
        fill_csr_kernel<<<(NEDGE + 255) / 256, 256>>>(a2p_src, a2p_dst, cnt, c1, NEDGE);
    }
    build_csr(p2a_src, p2a_dst, NAUTHOR, rp2, c2, cnt, bsums);
    build_csr(p2p_src, p2p_dst, NPAPER,  rp3, c3, cnt, bsums);

    ushortT *ypch = yph0, *ypcl = ypl0, *ypnh = yph1, *ypnl = ypl1;
    ushortT *yach = yah0, *yacl = yal0, *yanh = yah1, *yanl = yal1;
    const int GG = ((2 * NPAPER + NAUTHOR) * 32 + 255) / 256;

    for (int l = 0; l < 2; l++) {
        gather3_kernel<<<GG, 256>>>((const uint2*)yach, (const uint2*)yacl,
                                    (const uint2*)ypch, (const uint2*)ypcl,
                                    rp1, c1, (uint2*)mp1h, (uint2*)mp1l,
                                    rp3, c3, (uint2*)mp2h, (uint2*)mp2l,
                                    rp2, c2, (uint2*)mah,  (uint2*)mal);

        // new_p = m_a2p@Wl[l,0] + m_p2p@Wl[l,2] + yp@(Wr[l,0]+Wr[l,2]) + biases
        gemm_bf<128><<<GP, 512, S128>>>(
            mp1h, mp1l, 128, 0, wih + (3 + l * 3 + 0) * IMG, wil + (3 + l * 3 + 0) * IMG,
            mp2h, mp2l, 128, 0, wih + (3 + l * 3 + 2) * IMG, wil + (3 + l * 3 + 2) * IMG,
            ypch, ypcl, 128, 0, wih + (9 + l) * IMG,          wil + (9 + l) * IMG,
            3, NPAPER,
            bl + (size_t)(l * 3 + 0) * HD, bl + (size_t)(l * 3 + 2) * HD,
            nullptr, ypnh, ypnl, 0);

        // new_a = m_p2a@Wl[l,1] + ya@Wr[l,1] + bl[l,1]
        gemm_bf<128><<<GA, 512, S128>>>(
            mah,  mal,  128, 0, wih + (3 + l * 3 + 1) * IMG, wil + (3 + l * 3 + 1) * IMG,
            yach, yacl, 128, 0, wih + (11 + l) * IMG,         wil + (11 + l) * IMG,
            nullptr, nullptr, 0, 0, nullptr, nullptr,
            2, NAUTHOR,
            bl + (size_t)(l * 3 + 1) * HD, nullptr,
            nullptr, yanh, yanl, 0);

        ushortT* u;
        u = ypch; ypch = ypnh; ypnh = u;
        u = ypcl; ypcl = ypnl; ypnl = u;
        u = yach; yach = yanh; yanh = u;
        u = yacl; yacl = yanl; yanl = u;
    }

    // final classifier (N=64), f32 output
    gemm_bf<64><<<GP, 512, S64>>>(
        ypch, ypcl, 128, 0, wih + 13 * IMG, wil + 13 * IMG,
        nullptr, nullptr, 0, 0, nullptr, nullptr,
        nullptr, nullptr, 0, 0, nullptr, nullptr,
        1, NPAPER, lin_b, nullptr, out, nullptr, nullptr, 0);
}

// round 13
// speedup vs baseline: 1.0911x; 1.0911x over previous
#include <cuda_runtime.h>
#include <cuda_bf16.h>
#include <cstdint>
#include <cstddef>

// ---------------------------------------------------------------------------
// Problem constants
// ---------------------------------------------------------------------------
#define NPAPER  100000
#define NAUTHOR 50000
#define NEDGE   600000
#define HD      128
#define IMG     16384          // elements per weight image (128x128)
#define ROWP    72             // padded row stride (bf16 elems) in smem tiles

typedef unsigned short ushortT;

// ---------------------------------------------------------------------------
// Static scratch — all activations live as pre-split bf16 hi/lo pairs
// ---------------------------------------------------------------------------
__device__ ushortT g_xph[(size_t)NPAPER * 256];
__device__ ushortT g_xpl[(size_t)NPAPER * 256];
__device__ ushortT g_xah[(size_t)NAUTHOR * 128];
__device__ ushortT g_xal[(size_t)NAUTHOR * 128];
__device__ ushortT g_yph0[(size_t)NPAPER * HD];
__device__ ushortT g_ypl0[(size_t)NPAPER * HD];
__device__ ushortT g_yph1[(size_t)NPAPER * HD];
__device__ ushortT g_ypl1[(size_t)NPAPER * HD];
__device__ ushortT g_yah0[(size_t)NAUTHOR * HD];
__device__ ushortT g_yal0[(size_t)NAUTHOR * HD];
__device__ ushortT g_yah1[(size_t)NAUTHOR * HD];
__device__ ushortT g_yal1[(size_t)NAUTHOR * HD];
__device__ ushortT g_mp1h[(size_t)NPAPER * HD];
__device__ ushortT g_mp1l[(size_t)NPAPER * HD];
__device__ ushortT g_mp2h[(size_t)NPAPER * HD];
__device__ ushortT g_mp2l[(size_t)NPAPER * HD];
__device__ ushortT g_mah[(size_t)NAUTHOR * HD];
__device__ ushortT g_mal[(size_t)NAUTHOR * HD];

__device__ int g_rp_a2p[NPAPER + 1];
__device__ int g_rp_p2a[NAUTHOR + 1];
__device__ int g_rp_p2p[NPAPER + 1];
__device__ int g_col_a2p[NEDGE];
__device__ int g_col_p2a[NEDGE];
__device__ int g_col_p2p[NEDGE];
__device__ int g_cnt1[NPAPER];
__device__ int g_cnt2[NAUTHOR];
__device__ int g_cnt3[NPAPER];
__device__ int g_bsums[1024];   // 3 slices at 0 / 256 / 512

// Pre-split bf16 weight images, transposed to [n][k] (14 images)
__device__ ushortT g_wih[14 * IMG];
__device__ ushortT g_wil[14 * IMG];

// ---------------------------------------------------------------------------
// helpers
// ---------------------------------------------------------------------------
__device__ __forceinline__ uint32_t smem_u32(const void* p) {
    uint32_t a;
    asm("{ .reg .u64 t; cvta.to.shared.u64 t, %1; cvt.u32.u64 %0, t; }" : "=r"(a) : "l"(p));
    return a;
}
__device__ __forceinline__ void splitbf(float f, ushortT& h, float& lo) {
    __nv_bfloat16 b = __float2bfloat16(f);
    h = __bfloat16_as_ushort(b);
    lo = f - __bfloat162float(b);
}
__device__ __forceinline__ ushortT bf16of(float f) {
    __nv_bfloat16 b = __float2bfloat16(f);
    return __bfloat16_as_ushort(b);
}
__device__ __forceinline__ float2 bfp2f(uint32_t p) {
    __nv_bfloat162 b = *reinterpret_cast<__nv_bfloat162*>(&p);
    return __bfloat1622float2(b);
}

// mma.sync m16n8k16 row.col f32.bf16.bf16.f32  (baseline sm_80+)
__device__ __forceinline__ void mma16816(float* c, const uint32_t* a, const uint32_t* b) {
    asm volatile(
        "mma.sync.aligned.m16n8k16.row.col.f32.bf16.bf16.f32 "
        "{%0,%1,%2,%3}, {%4,%5,%6,%7}, {%8,%9}, {%0,%1,%2,%3};"
        : "+f"(c[0]), "+f"(c[1]), "+f"(c[2]), "+f"(c[3])
        : "r"(a[0]), "r"(a[1]), "r"(a[2]), "r"(a[3]), "r"(b[0]), "r"(b[1]));
}
// ldmatrix x4 (baseline sm_75+)
__device__ __forceinline__ void ldm_x4(uint32_t* r, uint32_t addr) {
    asm volatile("ldmatrix.sync.aligned.m8n8.x4.shared.b16 {%0,%1,%2,%3}, [%4];"
                 : "=r"(r[0]), "=r"(r[1]), "=r"(r[2]), "=r"(r[3]) : "r"(addr));
}
// cp.async 16B (baseline sm_80+)
__device__ __forceinline__ void cp16(uint32_t dst, const void* src) {
    asm volatile("cp.async.cg.shared.global [%0], [%1], 16;" :: "r"(dst), "l"(src));
}
#define CP_COMMIT() asm volatile("cp.async.commit_group;" ::: "memory")
#define CP_WAIT1()  asm volatile("cp.async.wait_group 1;"  ::: "memory")

__device__ __forceinline__ void store_split2(ushortT* Yh, ushortT* Yl, size_t idx, float2 o) {
    __nv_bfloat16 hx = __float2bfloat16(o.x), hy = __float2bfloat16(o.y);
    float lx = o.x - __bfloat162float(hx);
    float ly = o.y - __bfloat162float(hy);
    ushort2 hv, lv;
    hv.x = __bfloat16_as_ushort(hx); hv.y = __bfloat16_as_ushort(hy);
    lv.x = bf16of(lx); lv.y = bf16of(ly);
    *(ushort2*)(Yh + idx) = hv;
    *(ushort2*)(Yl + idx) = lv;
}

// ---------------------------------------------------------------------------
// GEMM job descriptor (passed by value; two jobs share one launch so the
// second job's CTAs fill the first job's tail wave)
// ---------------------------------------------------------------------------
struct Job {
    const ushortT *Ah0, *Al0, *Ah1, *Al1, *Ah2, *Al2;
    const ushortT *Wh0, *Wl0, *Wh1, *Wl1, *Wh2, *Wl2;
    int lda0, lda1, lda2, ko0, ko1, ko2;
    int nStages, nBlocks, M;
    const float *b0, *b1;
    float* Yf;
    ushortT *Yh, *Yl;
    int relu;
};

// ---------------------------------------------------------------------------
// Weight prep: split W into bf16 hi/lo, transposed to [n][k].
// ---------------------------------------------------------------------------
__global__ void prep_w_kernel(const float* __restrict__ lin_p_w, const float* __restrict__ lin_a_w,
                              const float* __restrict__ Wl, const float* __restrict__ Wr,
                              const float* __restrict__ lin_w,
                              ushortT* __restrict__ ih, ushortT* __restrict__ il) {
    int img = blockIdx.x;
    int N = (img == 13) ? 64 : 128;
    int total = N * 128;
    for (int i = threadIdx.x; i < total; i += blockDim.x) {
        int n = i / 128, k = i % 128;
        float w;
        if (img == 0)       w = lin_p_w[k * 128 + n];
        else if (img == 1)  w = lin_p_w[(k + 128) * 128 + n];
        else if (img == 2)  w = lin_a_w[k * 128 + n];
        else if (img <= 8)  w = Wl[(size_t)(img - 3) * IMG + k * 128 + n];
        else if (img <= 10) {
            int l = img - 9;
            w = Wr[(size_t)(l * 3 + 0) * IMG + k * 128 + n] +
                Wr[(size_t)(l * 3 + 2) * IMG + k * 128 + n];
        }
        else if (img <= 12) w = Wr[(size_t)((img - 11) * 3 + 1) * IMG + k * 128 + n];
        else                w = lin_w[k * 64 + n];
        ushortT h; float lo;
        splitbf(w, h, lo);
        size_t base = (size_t)img * IMG + (size_t)n * 128 + k;
        ih[base] = h;
        il[base] = bf16of(lo);
    }
}

// ---------------------------------------------------------------------------
// Input-feature split: x_paper/x_author -> bf16 hi/lo
// ---------------------------------------------------------------------------
__global__ void prep_x_kernel(const float* __restrict__ xp, const float* __restrict__ xa,
                              ushortT* __restrict__ xph, ushortT* __restrict__ xpl,
                              ushortT* __restrict__ xah, ushortT* __restrict__ xal) {
    const int NP_E = NPAPER * 256;
    const int NA_E = NAUTHOR * 128;
    int stride = gridDim.x * blockDim.x;
    for (int i = blockIdx.x * blockDim.x + threadIdx.x; i < NP_E + NA_E; i += stride) {
        if (i < NP_E) {
            ushortT h; float lo;
            splitbf(xp[i], h, lo);
            xph[i] = h; xpl[i] = bf16of(lo);
        } else {
            int j = i - NP_E;
            ushortT h; float lo;
            splitbf(xa[j], h, lo);
            xah[j] = h; xal[j] = bf16of(lo);
        }
    }
}

// ---------------------------------------------------------------------------
// Two-job pipelined split-bf16 tensor-core GEMM.  CTA = 512 threads,
// tile 128 x N, 16 warps (4m x 4n), double-buffered cp.async (R10 mainloop).
// ---------------------------------------------------------------------------
template<int N>
__global__ void __launch_bounds__(512, 1)
gemm_bf(Job ja, Job jb) {
    extern __shared__ char smem[];
    constexpr int NT = N / 32;
    constexpr int A_BYTES = 128 * ROWP * 2;
    constexpr int W_BYTES = N * ROWP * 2;
    constexpr int BUF = 2 * A_BYTES + 2 * W_BYTES;

    bool first = blockIdx.x < (unsigned)ja.nBlocks;
    const Job& J = first ? ja : jb;
    int blk = first ? blockIdx.x : blockIdx.x - ja.nBlocks;

    int tid = threadIdx.x, wid = tid >> 5, lane = tid & 31;
    int g = lane >> 2, t4 = lane & 3;
    int warp_m = wid & 3, warp_n = wid >> 2;
    int rowBase = blk * 128;
    int M = J.M;
    uint32_t sb = smem_u32(smem);

    const ushortT* Ahs[3] = {J.Ah0, J.Ah1, J.Ah2};
    const ushortT* Als[3] = {J.Al0, J.Al1, J.Al2};
    const ushortT* Whs[3] = {J.Wh0, J.Wh1, J.Wh2};
    const ushortT* Wls[3] = {J.Wl0, J.Wl1, J.Wl2};
    const int ldas[3] = {J.lda0, J.lda1, J.lda2};
    const int kos[3] = {J.ko0, J.ko1, J.ko2};

    uint32_t a_off = (uint32_t)((warp_m * 32 + (lane & 15)) * ROWP + ((lane >> 4) << 3)) * 2;
    uint32_t b_off = (uint32_t)((warp_n * (N / 4) + (lane & 7) + ((lane >> 4) << 3)) * ROWP
                                + (((lane >> 3) & 1) << 3)) * 2;

    auto issue = [&](int c, int buf) {
        int stage = c >> 1, half = c & 1;
        const ushortT* Ah = Ahs[stage];
        const ushortT* Al = Als[stage];
        const ushortT* Wh = Whs[stage];
        const ushortT* Wl = Wls[stage];
        int lda = ldas[stage];
        int koff = kos[stage] + half * 64;
        int kc = half * 64;
        uint32_t base = sb + (uint32_t)buf * BUF;
        const int total = (256 + 2 * N) * 8;
        for (int i = tid; i < total; i += 512) {
            int row = i >> 3, seg = i & 7;
            if (row < 128) {
                int grow = rowBase + row; if (grow > M - 1) grow = M - 1;
                cp16(base + row * 144 + seg * 16, Ah + (size_t)grow * lda + koff + seg * 8);
            } else if (row < 256) {
                int r = row - 128;
                int grow = rowBase + r; if (grow > M - 1) grow = M - 1;
                cp16(base + A_BYTES + r * 144 + seg * 16, Al + (size_t)grow * lda + koff + seg * 8);
            } else if (row < 256 + N) {
                int n = row - 256;
                cp16(base + 2 * A_BYTES + n * 144 + seg * 16, Wh + (size_t)n * 128 + kc + seg * 8);
            } else {
                int n = row - 256 - N;
                cp16(base + 2 * A_BYTES + W_BYTES + n * 144 + seg * 16,
                     Wl + (size_t)n * 128 + kc + seg * 8);
            }
        }
    };

    float acc[2][NT][4];
#pragma unroll
    for (int m = 0; m < 2; m++)
#pragma unroll
        for (int n = 0; n < NT; n++)
#pragma unroll
            for (int q = 0; q < 4; q++) acc[m][n][q] = 0.f;

    int nChunks = J.nStages * 2;
    issue(0, 0); CP_COMMIT();
    if (nChunks > 1) issue(1, 1);
    CP_COMMIT();

    for (int c = 0; c < nChunks; c++) {
        CP_WAIT1();
        __syncthreads();
        uint32_t bb = sb + (uint32_t)(c & 1) * BUF;
        uint32_t aH = bb + a_off, aL = aH + A_BYTES;
        uint32_t wH = bb + 2 * A_BYTES + b_off, wL = wH + W_BYTES;
#pragma unroll
        for (int k16 = 0; k16 < 64; k16 += 16) {
            uint32_t ah[2][4], al[2][4];
#pragma unroll
            for (int mt = 0; mt < 2; mt++) {
                uint32_t d = (uint32_t)(mt * 16 * ROWP + k16) * 2;
                ldm_x4(ah[mt], aH + d);
                ldm_x4(al[mt], aL + d);
            }
#pragma unroll
            for (int ntp = 0; ntp < NT / 2; ntp++) {
                uint32_t d = (uint32_t)(ntp * 16 * ROWP + k16) * 2;
                uint32_t bh[4], blo[4];
                ldm_x4(bh, wH + d);
                ldm_x4(blo, wL + d);
#pragma unroll
                for (int h2 = 0; h2 < 2; h2++) {
                    int nt = ntp * 2 + h2;
#pragma unroll
                    for (int mt = 0; mt < 2; mt++) {
                        mma16816(acc[mt][nt], ah[mt], bh + h2 * 2);
                        mma16816(acc[mt][nt], ah[mt], blo + h2 * 2);
                        mma16816(acc[mt][nt], al[mt], bh + h2 * 2);
                    }
                }
            }
        }
        __syncthreads();
        if (c + 2 < nChunks) issue(c + 2, c & 1);
        CP_COMMIT();
    }

    // --- epilogue: hi/lo bf16 (and/or f32) ---
#pragma unroll
    for (int mt = 0; mt < 2; mt++) {
        int r0 = rowBase + warp_m * 32 + mt * 16 + g;
        int r1 = r0 + 8;
#pragma unroll
        for (int nt = 0; nt < NT; nt++) {
            int col = warp_n * (N / 4) + nt * 8 + t4 * 2;
            float bx = J.b0[col], by = J.b0[col + 1];
            if (J.b1) { bx += J.b1[col]; by += J.b1[col + 1]; }
            float2 o0, o1;
            o0.x = acc[mt][nt][0] + bx; o0.y = acc[mt][nt][1] + by;
            o1.x = acc[mt][nt][2] + bx; o1.y = acc[mt][nt][3] + by;
            if (J.relu) {
                o0.x = fmaxf(o0.x, 0.f); o0.y = fmaxf(o0.y, 0.f);
                o1.x = fmaxf(o1.x, 0.f); o1.y = fmaxf(o1.y, 0.f);
            }
            if (r0 < M) {
                if (J.Yf) *(float2*)(J.Yf + (size_t)r0 * N + col) = o0;
                if (J.Yh) store_split2(J.Yh, J.Yl, (size_t)r0 * N + col, o0);
            }
            if (r1 < M) {
                if (J.Yf) *(float2*)(J.Yf + (size_t)r1 * N + col) = o1;
                if (J.Yh) store_split2(J.Yh, J.Yl, (size_t)r1 * N + col, o1);
            }
        }
    }
}

// ---------------------------------------------------------------------------
// Batched CSR build (3 edge types in 6 launches total)
// ---------------------------------------------------------------------------
__global__ void zero3_kernel(int* c1, int* c2, int* c3) {
    const int T = NPAPER + NAUTHOR + NPAPER;
    int stride = gridDim.x * blockDim.x;
    for (int i = blockIdx.x * blockDim.x + threadIdx.x; i < T; i += stride) {
        if (i < NPAPER) c1[i] = 0;
        else if (i < NPAPER + NAUTHOR) c2[i - NPAPER] = 0;
        else c3[i - NPAPER - NAUTHOR] = 0;
    }
}

__global__ void hist3_kernel(const int* d1, const int* d2, const int* d3,
                             int* c1, int* c2, int* c3) {
    int i = blockIdx.x * blockDim.x + threadIdx.x;
    if (i < NEDGE) atomicAdd(&c1[d1[i]], 1);
    else if (i < 2 * NEDGE) atomicAdd(&c2[d2[i - NEDGE]], 1);
    else if (i < 3 * NEDGE) atomicAdd(&c3[d3[i - 2 * NEDGE]], 1);
}

// Batched exclusive block scan over 3 segments.
__global__ void scanb3_kernel(const int* c1, const int* c2, const int* c3,
                              int* r1, int* r2, int* r3, int* bsums) {
    const int NB1 = (NPAPER + 1023) / 1024;   // 98
    const int NB2 = (NAUTHOR + 1023) / 1024;  // 49
    const int* in; int* out; int n, lb, slice;
    int b = blockIdx.x;
    if (b < NB1) { in = c1; out = r1; n = NPAPER; lb = b; slice = 0; }
    else if (b < NB1 + NB2) { in = c2; out = r2; n = NAUTHOR; lb = b - NB1; slice = 1; }
    else { in = c3; out = r3; n = NPAPER; lb = b - NB1 - NB2; slice = 2; }
    __shared__ int sh[1024];
    int gid = lb * 1024 + threadIdx.x;
    int v = (gid < n) ? in[gid] : 0;
    sh[threadIdx.x] = v;
    __syncthreads();
    for (int off = 1; off < 1024; off <<= 1) {
        int t = (threadIdx.x >= off) ? sh[threadIdx.x - off] : 0;
        __syncthreads();
        sh[threadIdx.x] += t;
        __syncthreads();
    }
    if (gid < n) out[gid] = sh[threadIdx.x] - v;
    if (threadIdx.x == 1023) bsums[slice * 256 + lb] = sh[1023];
}

// 3 blocks: block b scans its 256-slice of bsums in place.
__global__ void scanp3_kernel(int* bsums) {
    __shared__ int sh[256];
    int* s = bsums + blockIdx.x * 256;
    int v = s[threadIdx.x];
    sh[threadIdx.x] = v;
    __syncthreads();
    for (int off = 1; off < 256; off <<= 1) {
        int t = (threadIdx.x >= off) ? sh[threadIdx.x - off] : 0;
        __syncthreads();
        sh[threadIdx.x] += t;
        __syncthreads();
    }
    s[threadIdx.x] = sh[threadIdx.x] - v;
}

__global__ void scana3_kernel(int* r1, int* r2, int* r3,
                              int* c1, int* c2, int* c3, const int* bsums) {
    const int NB1 = (NPAPER + 1023) / 1024;
    const int NB2 = (NAUTHOR + 1023) / 1024;
    int* rp; int* cnt; int n, lb, slice;
    int b = blockIdx.x;
    if (b < NB1) { rp = r1; cnt = c1; n = NPAPER; lb = b; slice = 0; }
    else if (b < NB1 + NB2) { rp = r2; cnt = c2; n = NAUTHOR; lb = b - NB1; slice = 1; }
    else { rp = r3; cnt = c3; n = NPAPER; lb = b - NB1 - NB2; slice = 2; }
    int gid = lb * 1024 + threadIdx.x;
    if (gid < n) {
        int r = rp[gid] + bsums[slice * 256 + lb];
        rp[gid] = r;
        cnt[gid] = r;
    }
    if (gid == 0) rp[n] = NEDGE;
}

__global__ void fill3_kernel(const int* s1, const int* d1, int* c1, int* col1,
                             const int* s2, const int* d2, int* c2, int* col2,
                             const int* s3, const int* d3, int* c3, int* col3) {
    int i = blockIdx.x * blockDim.x + threadIdx.x;
    if (i < NEDGE) {
        int p = atomicAdd(&c1[d1[i]], 1);
        col1[p] = s1[i];
    } else if (i < 2 * NEDGE) {
        int j = i - NEDGE;
        int p = atomicAdd(&c2[d2[j]], 1);
        col2[p] = s2[j];
    } else if (i < 3 * NEDGE) {
        int j = i - 2 * NEDGE;
        int p = atomicAdd(&c3[d3[j]], 1);
        col3[p] = s3[j];
    }
}

// ---------------------------------------------------------------------------
// Fused 3-way gather-mean: consumes hi/lo bf16 features, emits hi/lo bf16.
// ---------------------------------------------------------------------------
__device__ __forceinline__ void gather_one(const uint2* __restrict__ fH,
                                           const uint2* __restrict__ fL,
                                           const int* __restrict__ rowptr,
                                           const int* __restrict__ col,
                                           uint2* __restrict__ outH, uint2* __restrict__ outL,
                                           int node, int lane) {
    int e0 = __ldg(&rowptr[node]);
    int e1 = __ldg(&rowptr[node + 1]);
    float4 a0 = make_float4(0.f, 0.f, 0.f, 0.f);
    float4 a1 = make_float4(0.f, 0.f, 0.f, 0.f);
    int e = e0;
    for (; e + 1 < e1; e += 2) {
        int s0 = __ldg(&col[e]);
        int s1 = __ldg(&col[e + 1]);
        uint2 h0 = fH[(size_t)s0 * 32 + lane];
        uint2 l0 = fL[(size_t)s0 * 32 + lane];
        uint2 h1 = fH[(size_t)s1 * 32 + lane];
        uint2 l1 = fL[(size_t)s1 * 32 + lane];
        float2 p0 = bfp2f(h0.x), p1 = bfp2f(h0.y), q0 = bfp2f(l0.x), q1 = bfp2f(l0.y);
        float2 r0 = bfp2f(h1.x), r1 = bfp2f(h1.y), s0f = bfp2f(l1.x), s1f = bfp2f(l1.y);
        a0.x += p0.x + q0.x; a0.y += p0.y + q0.y;
        a0.z += p1.x + q1.x; a0.w += p1.y + q1.y;
        a1.x += r0.x + s0f.x; a1.y += r0.y + s0f.y;
        a1.z += r1.x + s1f.x; a1.w += r1.y + s1f.y;
    }
    if (e < e1) {
        int s = __ldg(&col[e]);
        uint2 h = fH[(size_t)s * 32 + lane];
        uint2 l = fL[(size_t)s * 32 + lane];
        float2 p0 = bfp2f(h.x), p1 = bfp2f(h.y), q0 = bfp2f(l.x), q1 = bfp2f(l.y);
        a0.x += p0.x + q0.x; a0.y += p0.y + q0.y;
        a0.z += p1.x + q1.x; a0.w += p1.y + q1.y;
    }
    float inv = 1.0f / fmaxf((float)(e1 - e0), 1.0f);
    float o[4];
    o[0] = (a0.x + a1.x) * inv; o[1] = (a0.y + a1.y) * inv;
    o[2] = (a0.z + a1.z) * inv; o[3] = (a0.w + a1.w) * inv;
    ushortT h[4], lw[4];
    float lo;
#pragma unroll
    for (int q = 0; q < 4; q++) { splitbf(o[q], h[q], lo); lw[q] = bf16of(lo); }
    uint2 hv, lv;
    hv.x = (uint32_t)h[0] | ((uint32_t)h[1] << 16);
    hv.y = (uint32_t)h[2] | ((uint32_t)h[3] << 16);
    lv.x = (uint32_t)lw[0] | ((uint32_t)lw[1] << 16);
    lv.y = (uint32_t)lw[2] | ((uint32_t)lw[3] << 16);
    outH[(size_t)node * 32 + lane] = hv;
    outL[(size_t)node * 32 + lane] = lv;
}

__global__ void gather3_kernel(const uint2* __restrict__ fAh, const uint2* __restrict__ fAl,
                               const uint2* __restrict__ fPh, const uint2* __restrict__ fPl,
                               const int* __restrict__ rp1, const int* __restrict__ c1,
                               uint2* __restrict__ mp1h, uint2* __restrict__ mp1l,
                               const int* __restrict__ rp3, const int* __restrict__ c3,
                               uint2* __restrict__ mp2h, uint2* __restrict__ mp2l,
                               const int* __restrict__ rp2, const int* __restrict__ c2,
                               uint2* __restrict__ mah, uint2* __restrict__ mal) {
    int w = (blockIdx.x * blockDim.x + threadIdx.x) >> 5;
    int lane = threadIdx.x & 31;
    if (w < NPAPER) {
        gather_one(fAh, fAl, rp1, c1, mp1h, mp1l, w, lane);
    } else if (w < 2 * NPAPER) {
        gather_one(fPh, fPl, rp3, c3, mp2h, mp2l, w - NPAPER, lane);
    } else if (w < 2 * NPAPER + NAUTHOR) {
        gather_one(fPh, fPl, rp2, c2, mah, mal, w - 2 * NPAPER, lane);
    }
}

// ---------------------------------------------------------------------------
// Orchestration
// ---------------------------------------------------------------------------
extern "C" void kernel_launch(void* const* d_in, const int* in_sizes, int n_in,
                              void* d_out, int out_size) {
    const float* x_paper  = (const float*)d_in[0];
    const float* x_author = (const float*)d_in[1];
    const float* lin_p_w  = (const float*)d_in[2];
    const float* lin_p_b  = (const float*)d_in[3];
    const float* lin_a_w  = (const float*)d_in[4];
    const float* lin_a_b  = (const float*)d_in[5];
    const float* Wl       = (const float*)d_in[6];
    const float* bl       = (const float*)d_in[7];
    const float* Wr       = (const float*)d_in[8];
    const float* lin_w    = (const float*)d_in[9];
    const float* lin_b    = (const float*)d_in[10];
    const int* a2p_src = (const int*)d_in[11];
    const int* a2p_dst = (const int*)d_in[12];
    const int* p2a_src = (const int*)d_in[13];
    const int* p2a_dst = (const int*)d_in[14];
    const int* p2p_src = (const int*)d_in[15];
    const int* p2p_dst = (const int*)d_in[16];
    float* out = (float*)d_out;

    int *rp1, *rp2, *rp3, *c1, *c2, *c3, *cnt1, *cnt2, *cnt3, *bsums;
    ushortT *wih, *wil, *xph, *xpl, *xah, *xal;
    ushortT *yph0, *ypl0, *yph1, *ypl1, *yah0, *yal0, *yah1, *yal1;
    ushortT *mp1h, *mp1l, *mp2h, *mp2l, *mah, *mal;
    cudaGetSymbolAddress((void**)&rp1, g_rp_a2p);
    cudaGetSymbolAddress((void**)&rp2, g_rp_p2a);
    cudaGetSymbolAddress((void**)&rp3, g_rp_p2p);
    cudaGetSymbolAddress((void**)&c1,  g_col_a2p);
    cudaGetSymbolAddress((void**)&c2,  g_col_p2a);
    cudaGetSymbolAddress((void**)&c3,  g_col_p2p);
    cudaGetSymbolAddress((void**)&cnt1, g_cnt1);
    cudaGetSymbolAddress((void**)&cnt2, g_cnt2);
    cudaGetSymbolAddress((void**)&cnt3, g_cnt3);
    cudaGetSymbolAddress((void**)&bsums, g_bsums);
    cudaGetSymbolAddress((void**)&wih, g_wih);
    cudaGetSymbolAddress((void**)&wil, g_wil);
    cudaGetSymbolAddress((void**)&xph, g_xph);
    cudaGetSymbolAddress((void**)&xpl, g_xpl);
    cudaGetSymbolAddress((void**)&xah, g_xah);
    cudaGetSymbolAddress((void**)&xal, g_xal);
    cudaGetSymbolAddress((void**)&yph0, g_yph0);
    cudaGetSymbolAddress((void**)&ypl0, g_ypl0);
    cudaGetSymbolAddress((void**)&yph1, g_yph1);
    cudaGetSymbolAddress((void**)&ypl1, g_ypl1);
    cudaGetSymbolAddress((void**)&yah0, g_yah0);
    cudaGetSymbolAddress((void**)&yal0, g_yal0);
    cudaGetSymbolAddress((void**)&yah1, g_yah1);
    cudaGetSymbolAddress((void**)&yal1, g_yal1);
    cudaGetSymbolAddress((void**)&mp1h, g_mp1h);
    cudaGetSymbolAddress((void**)&mp1l, g_mp1l);
    cudaGetSymbolAddress((void**)&mp2h, g_mp2h);
    cudaGetSymbolAddress((void**)&mp2l, g_mp2l);
    cudaGetSymbolAddress((void**)&mah, g_mah);
    cudaGetSymbolAddress((void**)&mal, g_mal);

    const int BUF128 = 2 * 128 * ROWP * 2 + 2 * 128 * ROWP * 2;
    const int BUF64  = 2 * 128 * ROWP * 2 + 2 * 64 * ROWP * 2;
    const int S128 = 2 * BUF128;  // 147456
    const int S64  = 2 * BUF64;   // 110592
    cudaFuncSetAttribute(gemm_bf<128>, cudaFuncAttributeMaxDynamicSharedMemorySize, S128);
    cudaFuncSetAttribute(gemm_bf<64>,  cudaFuncAttributeMaxDynamicSharedMemorySize, S64);

    const int GP = (NPAPER + 127) / 128;   // 782
    const int GA = (NAUTHOR + 127) / 128;  // 391
    const int NB1 = (NPAPER + 1023) / 1024, NB2 = (NAUTHOR + 1023) / 1024;
    const int NBall = NB1 + NB2 + NB1;     // 245

    auto mkjob = [](const ushortT* ah0, const ushortT* al0, int lda0, int ko0,
                    const ushortT* wh0, const ushortT* wl0,
                    const ushortT* ah1, const ushortT* al1, int lda1, int ko1,
                    const ushortT* wh1, const ushortT* wl1,
                    const ushortT* ah2, const ushortT* al2, int lda2, int ko2,
                    const ushortT* wh2, const ushortT* wl2,
                    int nStages, int nBlocks, int M,
                    const float* b0, const float* b1,
                    float* yf, ushortT* yh, ushortT* yl, int relu) {
        Job j;
        j.Ah0 = ah0; j.Al0 = al0; j.Ah1 = ah1; j.Al1 = al1; j.Ah2 = ah2; j.Al2 = al2;
        j.Wh0 = wh0; j.Wl0 = wl0; j.Wh1 = wh1; j.Wl1 = wl1; j.Wh2 = wh2; j.Wl2 = wl2;
        j.lda0 = lda0; j.lda1 = lda1; j.lda2 = lda2;
        j.ko0 = ko0; j.ko1 = ko1; j.ko2 = ko2;
        j.nStages = nStages; j.nBlocks = nBlocks; j.M = M;
        j.b0 = b0; j.b1 = b1; j.Yf = yf; j.Yh = yh; j.Yl = yl; j.relu = relu;
        return j;
    };

    // 1: weight prep
    prep_w_kernel<<<14, 256>>>(lin_p_w, lin_a_w, Wl, Wr, lin_w, wih, wil);
    // 2: input split
    prep_x_kernel<<<4096, 256>>>(x_paper, x_author, xph, xpl, xah, xal);
    // 3: zero all 3 histogram arrays
    zero3_kernel<<<256, 256>>>(cnt1, cnt2, cnt3);
    // 4: combined projection GEMM (paper K=256, relu + author K=128, relu)
    {
        Job jp = mkjob(xph, xpl, 256, 0,   wih + 0 * IMG, wil + 0 * IMG,
                       xph, xpl, 256, 128, wih + 1 * IMG, wil + 1 * IMG,
                       nullptr, nullptr, 0, 0, nullptr, nullptr,
                       2, GP, NPAPER, lin_p_b, nullptr, nullptr, yph0, ypl0, 1);
        Job ja = mkjob(xah, xal, 128, 0, wih + 2 * IMG, wil + 2 * IMG,
                       nullptr, nullptr, 0, 0, nullptr, nullptr,
                       nullptr, nullptr, 0, 0, nullptr, nullptr,
                       1, GA, NAUTHOR, lin_a_b, nullptr, nullptr, yah0, yal0, 1);
        gemm_bf<128><<<GP + GA, 512, S128>>>(jp, ja);
    }
    // 5-9: batched CSR build
    hist3_kernel<<<(3 * NEDGE + 255) / 256, 256>>>(a2p_dst, p2a_dst, p2p_dst, cnt1, cnt2, cnt3);
    scanb3_kernel<<<NBall, 1024>>>(cnt1, cnt2, cnt3, rp1, rp2, rp3, bsums);
    scanp3_kernel<<<3, 256>>>(bsums);
    scana3_kernel<<<NBall, 1024>>>(rp1, rp2, rp3, cnt1, cnt2, cnt3, bsums);
    fill3_kernel<<<(3 * NEDGE + 255) / 256, 256>>>(a2p_src, a2p_dst, cnt1, c1,
                                                   p2a_src, p2a_dst, cnt2, c2,
                                                   p2p_src, p2p_dst, cnt3, c3);

    ushortT *ypch = yph0, *ypcl = ypl0, *ypnh = yph1, *ypnl = ypl1;
    ushortT *yach = yah0, *yacl = yal0, *yanh = yah1, *yanl = yal1;
    const int GG = ((2 * NPAPER + NAUTHOR) * 32 + 255) / 256;

    for (int l = 0; l < 2; l++) {
        gather3_kernel<<<GG, 256>>>((const uint2*)yach, (const uint2*)yacl,
                                    (const uint2*)ypch, (const uint2*)ypcl,
                                    rp1, c1, (uint2*)mp1h, (uint2*)mp1l,
                                    rp3, c3, (uint2*)mp2h, (uint2*)mp2l,
                                    rp2, c2, (uint2*)mah,  (uint2*)mal);

        // combined layer GEMM: paper update (3 stages) + author update (2 stages)
        Job jp = mkjob(mp1h, mp1l, 128, 0, wih + (3 + l * 3 + 0) * IMG, wil + (3 + l * 3 + 0) * IMG,
                       mp2h, mp2l, 128, 0, wih + (3 + l * 3 + 2) * IMG, wil + (3 + l * 3 + 2) * IMG,
                       ypch, ypcl, 128, 0, wih + (9 + l) * IMG,          wil + (9 + l) * IMG,
                       3, GP, NPAPER,
                       bl + (size_t)(l * 3 + 0) * HD, bl + (size_t)(l * 3 + 2) * HD,
                       nullptr, ypnh, ypnl, 0);
        Job ja = mkjob(mah,  mal,  128, 0, wih + (3 + l * 3 + 1) * IMG, wil + (3 + l * 3 + 1) * IMG,
                       yach, yacl, 128, 0, wih + (11 + l) * IMG,         wil + (11 + l) * IMG,
                       nullptr, nullptr, 0, 0, nullptr, nullptr,
                       2, GA, NAUTHOR,
                       bl + (size_t)(l * 3 + 1) * HD, nullptr,
                       nullptr, yanh, yanl, 0);
        gemm_bf<128><<<GP + GA, 512, S128>>>(jp, ja);

        ushortT* u;
        u = ypch; ypch = ypnh; ypnh = u;
        u = ypcl; ypcl = ypnl; ypnl = u;
        u = yach; yach = yanh; yanh = u;
        u = yacl; yacl = yanl; yanl = u;
    }

    // final classifier (N=64), f32 output
    {
        Job jc = mkjob(ypch, ypcl, 128, 0, wih + 13 * IMG, wil + 13 * IMG,
                       nullptr, nullptr, 0, 0, nullptr, nullptr,
                       nullptr, nullptr, 0, 0, nullptr, nullptr,
                       1, GP, NPAPER, lin_b, nullptr, out, nullptr, nullptr, 0);
        gemm_bf<64><<<GP, 512, S64>>>(jc, jc);
    }
}

// round 16
// speedup vs baseline: 1.0932x; 1.0019x over previous
#include <cuda_runtime.h>
#include <cuda_bf16.h>
#include <cstdint>
#include <cstddef>

// ---------------------------------------------------------------------------
// Problem constants
// ---------------------------------------------------------------------------
#define NPAPER  100000
#define NAUTHOR 50000
#define NEDGE   600000
#define HD      128
#define IMG     16384          // elements per weight image (128x128)
#define ROWP    72             // padded row stride (bf16 elems) in smem tiles

typedef unsigned short ushortT;

// ---------------------------------------------------------------------------
// Static scratch — all activations live as pre-split bf16 hi/lo pairs
// ---------------------------------------------------------------------------
__device__ ushortT g_xph[(size_t)NPAPER * 256];
__device__ ushortT g_xpl[(size_t)NPAPER * 256];
__device__ ushortT g_xah[(size_t)NAUTHOR * 128];
__device__ ushortT g_xal[(size_t)NAUTHOR * 128];
__device__ ushortT g_yph0[(size_t)NPAPER * HD];
__device__ ushortT g_ypl0[(size_t)NPAPER * HD];
__device__ ushortT g_yph1[(size_t)NPAPER * HD];
__device__ ushortT g_ypl1[(size_t)NPAPER * HD];
__device__ ushortT g_yah0[(size_t)NAUTHOR * HD];
__device__ ushortT g_yal0[(size_t)NAUTHOR * HD];
__device__ ushortT g_yah1[(size_t)NAUTHOR * HD];
__device__ ushortT g_yal1[(size_t)NAUTHOR * HD];
__device__ ushortT g_mp1h[(size_t)NPAPER * HD];
__device__ ushortT g_mp1l[(size_t)NPAPER * HD];
__device__ ushortT g_mp2h[(size_t)NPAPER * HD];
__device__ ushortT g_mp2l[(size_t)NPAPER * HD];
__device__ ushortT g_mah[(size_t)NAUTHOR * HD];
__device__ ushortT g_mal[(size_t)NAUTHOR * HD];

__device__ int g_rp_a2p[NPAPER + 1];
__device__ int g_rp_p2a[NAUTHOR + 1];
__device__ int g_rp_p2p[NPAPER + 1];
__device__ int g_col_a2p[NEDGE];
__device__ int g_col_p2a[NEDGE];
__device__ int g_col_p2p[NEDGE];
__device__ int g_cnt1[NPAPER];
__device__ int g_cnt2[NAUTHOR];
__device__ int g_cnt3[NPAPER];
__device__ int g_bsums[1024];   // 3 slices at 0 / 256 / 512

// Pre-split bf16 weight images, transposed to [n][k] (14 images)
__device__ ushortT g_wih[14 * IMG];
__device__ ushortT g_wil[14 * IMG];

// ---------------------------------------------------------------------------
// helpers
// ---------------------------------------------------------------------------
__device__ __forceinline__ uint32_t smem_u32(const void* p) {
    uint32_t a;
    asm("{ .reg .u64 t; cvta.to.shared.u64 t, %1; cvt.u32.u64 %0, t; }" : "=r"(a) : "l"(p));
    return a;
}
__device__ __forceinline__ void splitbf(float f, ushortT& h, float& lo) {
    __nv_bfloat16 b = __float2bfloat16(f);
    h = __bfloat16_as_ushort(b);
    lo = f - __bfloat162float(b);
}
__device__ __forceinline__ ushortT bf16of(float f) {
    __nv_bfloat16 b = __float2bfloat16(f);
    return __bfloat16_as_ushort(b);
}
__device__ __forceinline__ float2 bfp2f(uint32_t p) {
    __nv_bfloat162 b = *reinterpret_cast<__nv_bfloat162*>(&p);
    return __bfloat1622float2(b);
}

// mma.sync m16n8k16 row.col f32.bf16.bf16.f32  (baseline sm_80+)
__device__ __forceinline__ void mma16816(float* c, const uint32_t* a, const uint32_t* b) {
    asm volatile(
        "mma.sync.aligned.m16n8k16.row.col.f32.bf16.bf16.f32 "
        "{%0,%1,%2,%3}, {%4,%5,%6,%7}, {%8,%9}, {%0,%1,%2,%3};"
        : "+f"(c[0]), "+f"(c[1]), "+f"(c[2]), "+f"(c[3])
        : "r"(a[0]), "r"(a[1]), "r"(a[2]), "r"(a[3]), "r"(b[0]), "r"(b[1]));
}
// ldmatrix x4 (baseline sm_75+)
__device__ __forceinline__ void ldm_x4(uint32_t* r, uint32_t addr) {
    asm volatile("ldmatrix.sync.aligned.m8n8.x4.shared.b16 {%0,%1,%2,%3}, [%4];"
                 : "=r"(r[0]), "=r"(r[1]), "=r"(r[2]), "=r"(r[3]) : "r"(addr));
}
// cp.async 16B (baseline sm_80+)
__device__ __forceinline__ void cp16(uint32_t dst, const void* src) {
    asm volatile("cp.async.cg.shared.global [%0], [%1], 16;" :: "r"(dst), "l"(src));
}
#define CP_COMMIT() asm volatile("cp.async.commit_group;" ::: "memory")
#define CP_WAIT1()  asm volatile("cp.async.wait_group 1;"  ::: "memory")

__device__ __forceinline__ void store_split2(ushortT* Yh, ushortT* Yl, size_t idx, float2 o) {
    __nv_bfloat16 hx = __float2bfloat16(o.x), hy = __float2bfloat16(o.y);
    float lx = o.x - __bfloat162float(hx);
    float ly = o.y - __bfloat162float(hy);
    ushort2 hv, lv;
    hv.x = __bfloat16_as_ushort(hx); hv.y = __bfloat16_as_ushort(hy);
    lv.x = bf16of(lx); lv.y = bf16of(ly);
    *(ushort2*)(Yh + idx) = hv;
    *(ushort2*)(Yl + idx) = lv;
}

// ---------------------------------------------------------------------------
// GEMM job descriptor (two jobs share one launch; second fills first's tail)
// ---------------------------------------------------------------------------
struct Job {
    const ushortT *Ah0, *Al0, *Ah1, *Al1, *Ah2, *Al2;
    const ushortT *Wh0, *Wl0, *Wh1, *Wl1, *Wh2, *Wl2;
    int lda0, lda1, lda2, ko0, ko1, ko2;
    int nStages, nBlocks, M;
    const float *b0, *b1;
    float* Yf;
    ushortT *Yh, *Yl;
    int relu;
};

// ---------------------------------------------------------------------------
// Weight prep: split W into bf16 hi/lo, transposed to [n][k].  (R13)
// ---------------------------------------------------------------------------
__global__ void prep_w_kernel(const float* __restrict__ lin_p_w, const float* __restrict__ lin_a_w,
                              const float* __restrict__ Wl, const float* __restrict__ Wr,
                              const float* __restrict__ lin_w,
                              ushortT* __restrict__ ih, ushortT* __restrict__ il) {
    int img = blockIdx.x;
    int N = (img == 13) ? 64 : 128;
    int total = N * 128;
    for (int i = threadIdx.x; i < total; i += blockDim.x) {
        int n = i / 128, k = i % 128;
        float w;
        if (img == 0)       w = lin_p_w[k * 128 + n];
        else if (img == 1)  w = lin_p_w[(k + 128) * 128 + n];
        else if (img == 2)  w = lin_a_w[k * 128 + n];
        else if (img <= 8)  w = Wl[(size_t)(img - 3) * IMG + k * 128 + n];
        else if (img <= 10) {
            int l = img - 9;
            w = Wr[(size_t)(l * 3 + 0) * IMG + k * 128 + n] +
                Wr[(size_t)(l * 3 + 2) * IMG + k * 128 + n];
        }
        else if (img <= 12) w = Wr[(size_t)((img - 11) * 3 + 1) * IMG + k * 128 + n];
        else                w = lin_w[k * 64 + n];
        ushortT h; float lo;
        splitbf(w, h, lo);
        size_t base = (size_t)img * IMG + (size_t)n * 128 + k;
        ih[base] = h;
        il[base] = bf16of(lo);
    }
}

// ---------------------------------------------------------------------------
// Input-feature split: x_paper/x_author -> bf16 hi/lo  (R13)
// ---------------------------------------------------------------------------
__global__ void prep_x_kernel(const float* __restrict__ xp, const float* __restrict__ xa,
                              ushortT* __restrict__ xph, ushortT* __restrict__ xpl,
                              ushortT* __restrict__ xah, ushortT* __restrict__ xal) {
    const int NP_E = NPAPER * 256;
    const int NA_E = NAUTHOR * 128;
    int stride = gridDim.x * blockDim.x;
    for (int i = blockIdx.x * blockDim.x + threadIdx.x; i < NP_E + NA_E; i += stride) {
        if (i < NP_E) {
            ushortT h; float lo;
            splitbf(xp[i], h, lo);
            xph[i] = h; xpl[i] = bf16of(lo);
        } else {
            int j = i - NP_E;
            ushortT h; float lo;
            splitbf(xa[j], h, lo);
            xah[j] = h; xal[j] = bf16of(lo);
        }
    }
}

__global__ void zero3_kernel(int* c1, int* c2, int* c3) {
    const int T = NPAPER + NAUTHOR + NPAPER;
    int stride = gridDim.x * blockDim.x;
    for (int i = blockIdx.x * blockDim.x + threadIdx.x; i < T; i += stride) {
        if (i < NPAPER) c1[i] = 0;
        else if (i < NPAPER + NAUTHOR) c2[i - NPAPER] = 0;
        else c3[i - NPAPER - NAUTHOR] = 0;
    }
}

// ---------------------------------------------------------------------------
// Two-job pipelined split-bf16 tensor-core GEMM (R13, unchanged).
// ---------------------------------------------------------------------------
template<int N>
__global__ void __launch_bounds__(512, 1)
gemm_bf(Job ja, Job jb) {
    extern __shared__ char smem[];
    constexpr int NT = N / 32;
    constexpr int A_BYTES = 128 * ROWP * 2;
    constexpr int W_BYTES = N * ROWP * 2;
    constexpr int BUF = 2 * A_BYTES + 2 * W_BYTES;

    bool first = blockIdx.x < (unsigned)ja.nBlocks;
    const Job& J = first ? ja : jb;
    int blk = first ? blockIdx.x : blockIdx.x - ja.nBlocks;

    int tid = threadIdx.x, wid = tid >> 5, lane = tid & 31;
    int g = lane >> 2, t4 = lane & 3;
    int warp_m = wid & 3, warp_n = wid >> 2;
    int rowBase = blk * 128;
    int M = J.M;
    uint32_t sb = smem_u32(smem);

    const ushortT* Ahs[3] = {J.Ah0, J.Ah1, J.Ah2};
    const ushortT* Als[3] = {J.Al0, J.Al1, J.Al2};
    const ushortT* Whs[3] = {J.Wh0, J.Wh1, J.Wh2};
    const ushortT* Wls[3] = {J.Wl0, J.Wl1, J.Wl2};
    const int ldas[3] = {J.lda0, J.lda1, J.lda2};
    const int kos[3] = {J.ko0, J.ko1, J.ko2};

    uint32_t a_off = (uint32_t)((warp_m * 32 + (lane & 15)) * ROWP + ((lane >> 4) << 3)) * 2;
    uint32_t b_off = (uint32_t)((warp_n * (N / 4) + (lane & 7) + ((lane >> 4) << 3)) * ROWP
                                + (((lane >> 3) & 1) << 3)) * 2;

    auto issue = [&](int c, int buf) {
        int stage = c >> 1, half = c & 1;
        const ushortT* Ah = Ahs[stage];
        const ushortT* Al = Als[stage];
        const ushortT* Wh = Whs[stage];
        const ushortT* Wl = Wls[stage];
        int lda = ldas[stage];
        int koff = kos[stage] + half * 64;
        int kc = half * 64;
        uint32_t base = sb + (uint32_t)buf * BUF;
        const int total = (256 + 2 * N) * 8;
        for (int i = tid; i < total; i += 512) {
            int row = i >> 3, seg = i & 7;
            if (row < 128) {
                int grow = rowBase + row; if (grow > M - 1) grow = M - 1;
                cp16(base + row * 144 + seg * 16, Ah + (size_t)grow * lda + koff + seg * 8);
            } else if (row < 256) {
                int r = row - 128;
                int grow = rowBase + r; if (grow > M - 1) grow = M - 1;
                cp16(base + A_BYTES + r * 144 + seg * 16, Al + (size_t)grow * lda + koff + seg * 8);
            } else if (row < 256 + N) {
                int n = row - 256;
                cp16(base + 2 * A_BYTES + n * 144 + seg * 16, Wh + (size_t)n * 128 + kc + seg * 8);
            } else {
                int n = row - 256 - N;
                cp16(base + 2 * A_BYTES + W_BYTES + n * 144 + seg * 16,
                     Wl + (size_t)n * 128 + kc + seg * 8);
            }
        }
    };

    float acc[2][NT][4];
#pragma unroll
    for (int m = 0; m < 2; m++)
#pragma unroll
        for (int n = 0; n < NT; n++)
#pragma unroll
            for (int q = 0; q < 4; q++) acc[m][n][q] = 0.f;

    int nChunks = J.nStages * 2;
    issue(0, 0); CP_COMMIT();
    if (nChunks > 1) issue(1, 1);
    CP_COMMIT();

    for (int c = 0; c < nChunks; c++) {
        CP_WAIT1();
        __syncthreads();
        uint32_t bb = sb + (uint32_t)(c & 1) * BUF;
        uint32_t aH = bb + a_off, aL = aH + A_BYTES;
        uint32_t wH = bb + 2 * A_BYTES + b_off, wL = wH + W_BYTES;
#pragma unroll
        for (int k16 = 0; k16 < 64; k16 += 16) {
            uint32_t ah[2][4], al[2][4];
#pragma unroll
            for (int mt = 0; mt < 2; mt++) {
                uint32_t d = (uint32_t)(mt * 16 * ROWP + k16) * 2;
                ldm_x4(ah[mt], aH + d);
                ldm_x4(al[mt], aL + d);
            }
#pragma unroll
            for (int ntp = 0; ntp < NT / 2; ntp++) {
                uint32_t d = (uint32_t)(ntp * 16 * ROWP + k16) * 2;
                uint32_t bh[4], blo[4];
                ldm_x4(bh, wH + d);
                ldm_x4(blo, wL + d);
#pragma unroll
                for (int h2 = 0; h2 < 2; h2++) {
                    int nt = ntp * 2 + h2;
#pragma unroll
                    for (int mt = 0; mt < 2; mt++) {
                        mma16816(acc[mt][nt], ah[mt], bh + h2 * 2);
                        mma16816(acc[mt][nt], ah[mt], blo + h2 * 2);
                        mma16816(acc[mt][nt], al[mt], bh + h2 * 2);
                    }
                }
            }
        }
        __syncthreads();
        if (c + 2 < nChunks) issue(c + 2, c & 1);
        CP_COMMIT();
    }

#pragma unroll
    for (int mt = 0; mt < 2; mt++) {
        int r0 = rowBase + warp_m * 32 + mt * 16 + g;
        int r1 = r0 + 8;
#pragma unroll
        for (int nt = 0; nt < NT; nt++) {
            int col = warp_n * (N / 4) + nt * 8 + t4 * 2;
            float bx = J.b0[col], by = J.b0[col + 1];
            if (J.b1) { bx += J.b1[col]; by += J.b1[col + 1]; }
            float2 o0, o1;
            o0.x = acc[mt][nt][0] + bx; o0.y = acc[mt][nt][1] + by;
            o1.x = acc[mt][nt][2] + bx; o1.y = acc[mt][nt][3] + by;
            if (J.relu) {
                o0.x = fmaxf(o0.x, 0.f); o0.y = fmaxf(o0.y, 0.f);
                o1.x = fmaxf(o1.x, 0.f); o1.y = fmaxf(o1.y, 0.f);
            }
            if (r0 < M) {
                if (J.Yf) *(float2*)(J.Yf + (size_t)r0 * N + col) = o0;
                if (J.Yh) store_split2(J.Yh, J.Yl, (size_t)r0 * N + col, o0);
            }
            if (r1 < M) {
                if (J.Yf) *(float2*)(J.Yf + (size_t)r1 * N + col) = o1;
                if (J.Yh) store_split2(J.Yh, J.Yl, (size_t)r1 * N + col, o1);
            }
        }
    }
}

// ---------------------------------------------------------------------------
// Batched CSR build (R13, unchanged)
// ---------------------------------------------------------------------------
__global__ void hist3_kernel(const int* d1, const int* d2, const int* d3,
                             int* c1, int* c2, int* c3) {
    int i = blockIdx.x * blockDim.x + threadIdx.x;
    if (i < NEDGE) atomicAdd(&c1[d1[i]], 1);
    else if (i < 2 * NEDGE) atomicAdd(&c2[d2[i - NEDGE]], 1);
    else if (i < 3 * NEDGE) atomicAdd(&c3[d3[i - 2 * NEDGE]], 1);
}

__global__ void scanb3_kernel(const int* c1, const int* c2, const int* c3,
                              int* r1, int* r2, int* r3, int* bsums) {
    const int NB1 = (NPAPER + 1023) / 1024;
    const int NB2 = (NAUTHOR + 1023) / 1024;
    const int* in; int* out; int n, lb, slice;
    int b = blockIdx.x;
    if (b < NB1) { in = c1; out = r1; n = NPAPER; lb = b; slice = 0; }
    else if (b < NB1 + NB2) { in = c2; out = r2; n = NAUTHOR; lb = b - NB1; slice = 1; }
    else { in = c3; out = r3; n = NPAPER; lb = b - NB1 - NB2; slice = 2; }
    __shared__ int sh[1024];
    int gid = lb * 1024 + threadIdx.x;
    int v = (gid < n) ? in[gid] : 0;
    sh[threadIdx.x] = v;
    __syncthreads();
    for (int off = 1; off < 1024; off <<= 1) {
        int t = (threadIdx.x >= off) ? sh[threadIdx.x - off] : 0;
        __syncthreads();
        sh[threadIdx.x] += t;
        __syncthreads();
    }
    if (gid < n) out[gid] = sh[threadIdx.x] - v;
    if (threadIdx.x == 1023) bsums[slice * 256 + lb] = sh[1023];
}

__global__ void scanp3_kernel(int* bsums) {
    __shared__ int sh[256];
    int* s = bsums + blockIdx.x * 256;
    int v = s[threadIdx.x];
    sh[threadIdx.x] = v;
    __syncthreads();
    for (int off = 1; off < 256; off <<= 1) {
        int t = (threadIdx.x >= off) ? sh[threadIdx.x - off] : 0;
        __syncthreads();
        sh[threadIdx.x] += t;
        __syncthreads();
    }
    s[threadIdx.x] = sh[threadIdx.x] - v;
}

__global__ void scana3_kernel(int* r1, int* r2, int* r3,
                              int* c1, int* c2, int* c3, const int* bsums) {
    const int NB1 = (NPAPER + 1023) / 1024;
    const int NB2 = (NAUTHOR + 1023) / 1024;
    int* rp; int* cnt; int n, lb, slice;
    int b = blockIdx.x;
    if (b < NB1) { rp = r1; cnt = c1; n = NPAPER; lb = b; slice = 0; }
    else if (b < NB1 + NB2) { rp = r2; cnt = c2; n = NAUTHOR; lb = b - NB1; slice = 1; }
    else { rp = r3; cnt = c3; n = NPAPER; lb = b - NB1 - NB2; slice = 2; }
    int gid = lb * 1024 + threadIdx.x;
    if (gid < n) {
        int r = rp[gid] + bsums[slice * 256 + lb];
        rp[gid] = r;
        cnt[gid] = r;
    }
    if (gid == 0) rp[n] = NEDGE;
}

__global__ void fill3_kernel(const int* s1, const int* d1, int* c1, int* col1,
                             const int* s2, const int* d2, int* c2, int* col2,
                             const int* s3, const int* d3, int* c3, int* col3) {
    int i = blockIdx.x * blockDim.x + threadIdx.x;
    if (i < NEDGE) {
        int p = atomicAdd(&c1[d1[i]], 1);
        col1[p] = s1[i];
    } else if (i < 2 * NEDGE) {
        int j = i - NEDGE;
        int p = atomicAdd(&c2[d2[j]], 1);
        col2[p] = s2[j];
    } else if (i < 3 * NEDGE) {
        int j = i - 2 * NEDGE;
        int p = atomicAdd(&c3[d3[j]], 1);
        col3[p] = s3[j];
    }
}

// ---------------------------------------------------------------------------
// Fused 3-way gather-mean, unroll-4 (8 independent feature loads in flight).
// ---------------------------------------------------------------------------
__device__ __forceinline__ void gather_one(const uint2* __restrict__ fH,
                                           const uint2* __restrict__ fL,
                                           const int* __restrict__ rowptr,
                                           const int* __restrict__ col,
                                           uint2* __restrict__ outH, uint2* __restrict__ outL,
                                           int node, int lane) {
    int e0 = __ldg(&rowptr[node]);
    int e1 = __ldg(&rowptr[node + 1]);
    float4 a0 = make_float4(0.f, 0.f, 0.f, 0.f);
    float4 a1 = make_float4(0.f, 0.f, 0.f, 0.f);
    int e = e0;
    for (; e + 3 < e1; e += 4) {
        int s0 = __ldg(&col[e]);
        int s1 = __ldg(&col[e + 1]);
        int s2 = __ldg(&col[e + 2]);
        int s3 = __ldg(&col[e + 3]);
        uint2 h0 = fH[(size_t)s0 * 32 + lane];
        uint2 l0 = fL[(size_t)s0 * 32 + lane];
        uint2 h1 = fH[(size_t)s1 * 32 + lane];
        uint2 l1 = fL[(size_t)s1 * 32 + lane];
        uint2 h2 = fH[(size_t)s2 * 32 + lane];
        uint2 l2 = fL[(size_t)s2 * 32 + lane];
        uint2 h3 = fH[(size_t)s3 * 32 + lane];
        uint2 l3 = fL[(size_t)s3 * 32 + lane];
        float2 v;
        v = bfp2f(h0.x); a0.x += v.x; a0.y += v.y;
        v = bfp2f(h0.y); a0.z += v.x; a0.w += v.y;
        v = bfp2f(l0.x); a0.x += v.x; a0.y += v.y;
        v = bfp2f(l0.y); a0.z += v.x; a0.w += v.y;
        v = bfp2f(h1.x); a1.x += v.x; a1.y += v.y;
        v = bfp2f(h1.y); a1.z += v.x; a1.w += v.y;
        v = bfp2f(l1.x); a1.x += v.x; a1.y += v.y;
        v = bfp2f(l1.y); a1.z += v.x; a1.w += v.y;
        v = bfp2f(h2.x); a0.x += v.x; a0.y += v.y;
        v = bfp2f(h2.y); a0.z += v.x; a0.w += v.y;
        v = bfp2f(l2.x); a0.x += v.x; a0.y += v.y;
        v = bfp2f(l2.y); a0.z += v.x; a0.w += v.y;
        v = bfp2f(h3.x); a1.x += v.x; a1.y += v.y;
        v = bfp2f(h3.y); a1.z += v.x; a1.w += v.y;
        v = bfp2f(l3.x); a1.x += v.x; a1.y += v.y;
        v = bfp2f(l3.y); a1.z += v.x; a1.w += v.y;
    }
    for (; e < e1; e++) {
        int s = __ldg(&col[e]);
        uint2 h = fH[(size_t)s * 32 + lane];
        uint2 l = fL[(size_t)s * 32 + lane];
        float2 v;
        v = bfp2f(h.x); a0.x += v.x; a0.y += v.y;
        v = bfp2f(h.y); a0.z += v.x; a0.w += v.y;
        v = bfp2f(l.x); a0.x += v.x; a0.y += v.y;
        v = bfp2f(l.y); a0.z += v.x; a0.w += v.y;
    }
    float inv = 1.0f / fmaxf((float)(e1 - e0), 1.0f);
    float o[4];
    o[0] = (a0.x + a1.x) * inv; o[1] = (a0.y + a1.y) * inv;
    o[2] = (a0.z + a1.z) * inv; o[3] = (a0.w + a1.w) * inv;
    ushortT h[4], lw[4];
    float lo;
#pragma unroll
    for (int q = 0; q < 4; q++) { splitbf(o[q], h[q], lo); lw[q] = bf16of(lo); }
    uint2 hv, lv;
    hv.x = (uint32_t)h[0] | ((uint32_t)h[1] << 16);
    hv.y = (uint32_t)h[2] | ((uint32_t)h[3] << 16);
    lv.x = (uint32_t)lw[0] | ((uint32_t)lw[1] << 16);
    lv.y = (uint32_t)lw[2] | ((uint32_t)lw[3] << 16);
    outH[(size_t)node * 32 + lane] = hv;
    outL[(size_t)node * 32 + lane] = lv;
}

__global__ void gather3_kernel(const uint2* __restrict__ fAh, const uint2* __restrict__ fAl,
                               const uint2* __restrict__ fPh, const uint2* __restrict__ fPl,
                               const int* __restrict__ rp1, const int* __restrict__ c1,
                               uint2* __restrict__ mp1h, uint2* __restrict__ mp1l,
                               const int* __restrict__ rp3, const int* __restrict__ c3,
                               uint2* __restrict__ mp2h, uint2* __restrict__ mp2l,
                               const int* __restrict__ rp2, const int* __restrict__ c2,
                               uint2* __restrict__ mah, uint2* __restrict__ mal) {
    int w = (blockIdx.x * blockDim.x + threadIdx.x) >> 5;
    int lane = threadIdx.x & 31;
    if (w < NPAPER) {
        gather_one(fAh, fAl, rp1, c1, mp1h, mp1l, w, lane);
    } else if (w < 2 * NPAPER) {
        gather_one(fPh, fPl, rp3, c3, mp2h, mp2l, w - NPAPER, lane);
    } else if (w < 2 * NPAPER + NAUTHOR) {
        gather_one(fPh, fPl, rp2, c2, mah, mal, w - 2 * NPAPER, lane);
    }
}

// ---------------------------------------------------------------------------
// Orchestration (R13 launch structure)
// ---------------------------------------------------------------------------
extern "C" void kernel_launch(void* const* d_in, const int* in_sizes, int n_in,
                              void* d_out, int out_size) {
    const float* x_paper  = (const float*)d_in[0];
    const float* x_author = (const float*)d_in[1];
    const float* lin_p_w  = (const float*)d_in[2];
    const float* lin_p_b  = (const float*)d_in[3];
    const float* lin_a_w  = (const float*)d_in[4];
    const float* lin_a_b  = (const float*)d_in[5];
    const float* Wl       = (const float*)d_in[6];
    const float* bl       = (const float*)d_in[7];
    const float* Wr       = (const float*)d_in[8];
    const float* lin_w    = (const float*)d_in[9];
    const float* lin_b    = (const float*)d_in[10];
    const int* a2p_src = (const int*)d_in[11];
    const int* a2p_dst = (const int*)d_in[12];
    const int* p2a_src = (const int*)d_in[13];
    const int* p2a_dst = (const int*)d_in[14];
    const int* p2p_src = (const int*)d_in[15];
    const int* p2p_dst = (const int*)d_in[16];
    float* out = (float*)d_out;

    int *rp1, *rp2, *rp3, *c1, *c2, *c3, *cnt1, *cnt2, *cnt3, *bsums;
    ushortT *wih, *wil, *xph, *xpl, *xah, *xal;
    ushortT *yph0, *ypl0, *yph1, *ypl1, *yah0, *yal0, *yah1, *yal1;
    ushortT *mp1h, *mp1l, *mp2h, *mp2l, *mah, *mal;
    cudaGetSymbolAddress((void**)&rp1, g_rp_a2p);
    cudaGetSymbolAddress((void**)&rp2, g_rp_p2a);
    cudaGetSymbolAddress((void**)&rp3, g_rp_p2p);
    cudaGetSymbolAddress((void**)&c1,  g_col_a2p);
    cudaGetSymbolAddress((void**)&c2,  g_col_p2a);
    cudaGetSymbolAddress((void**)&c3,  g_col_p2p);
    cudaGetSymbolAddress((void**)&cnt1, g_cnt1);
    cudaGetSymbolAddress((void**)&cnt2, g_cnt2);
    cudaGetSymbolAddress((void**)&cnt3, g_cnt3);
    cudaGetSymbolAddress((void**)&bsums, g_bsums);
    cudaGetSymbolAddress((void**)&wih, g_wih);
    cudaGetSymbolAddress((void**)&wil, g_wil);
    cudaGetSymbolAddress((void**)&xph, g_xph);
    cudaGetSymbolAddress((void**)&xpl, g_xpl);
    cudaGetSymbolAddress((void**)&xah, g_xah);
    cudaGetSymbolAddress((void**)&xal, g_xal);
    cudaGetSymbolAddress((void**)&yph0, g_yph0);
    cudaGetSymbolAddress((void**)&ypl0, g_ypl0);
    cudaGetSymbolAddress((void**)&yph1, g_yph1);
    cudaGetSymbolAddress((void**)&ypl1, g_ypl1);
    cudaGetSymbolAddress((void**)&yah0, g_yah0);
    cudaGetSymbolAddress((void**)&yal0, g_yal0);
    cudaGetSymbolAddress((void**)&yah1, g_yah1);
    cudaGetSymbolAddress((void**)&yal1, g_yal1);
    cudaGetSymbolAddress((void**)&mp1h, g_mp1h);
    cudaGetSymbolAddress((void**)&mp1l, g_mp1l);
    cudaGetSymbolAddress((void**)&mp2h, g_mp2h);
    cudaGetSymbolAddress((void**)&mp2l, g_mp2l);
    cudaGetSymbolAddress((void**)&mah, g_mah);
    cudaGetSymbolAddress((void**)&mal, g_mal);

    const int BUF128 = 2 * 128 * ROWP * 2 + 2 * 128 * ROWP * 2;
    const int BUF64  = 2 * 128 * ROWP * 2 + 2 * 64 * ROWP * 2;
    const int S128 = 2 * BUF128;  // 147456
    const int S64  = 2 * BUF64;   // 110592
    cudaFuncSetAttribute(gemm_bf<128>, cudaFuncAttributeMaxDynamicSharedMemorySize, S128);
    cudaFuncSetAttribute(gemm_bf<64>,  cudaFuncAttributeMaxDynamicSharedMemorySize, S64);

    const int GP = (NPAPER + 127) / 128;   // 782
    const int GA = (NAUTHOR + 127) / 128;  // 391
    const int NB1 = (NPAPER + 1023) / 1024, NB2 = (NAUTHOR + 1023) / 1024;
    const int NBall = NB1 + NB2 + NB1;     // 245

    auto mkjob = [](const ushortT* ah0, const ushortT* al0, int lda0, int ko0,
                    const ushortT* wh0, const ushortT* wl0,
                    const ushortT* ah1, const ushortT* al1, int lda1, int ko1,
                    const ushortT* wh1, const ushortT* wl1,
                    const ushortT* ah2, const ushortT* al2, int lda2, int ko2,
                    const ushortT* wh2, const ushortT* wl2,
                    int nStages, int nBlocks, int M,
                    const float* b0, const float* b1,
                    float* yf, ushortT* yh, ushortT* yl, int relu) {
        Job j;
        j.Ah0 = ah0; j.Al0 = al0; j.Ah1 = ah1; j.Al1 = al1; j.Ah2 = ah2; j.Al2 = al2;
        j.Wh0 = wh0; j.Wl0 = wl0; j.Wh1 = wh1; j.Wl1 = wl1; j.Wh2 = wh2; j.Wl2 = wl2;
        j.lda0 = lda0; j.lda1 = lda1; j.lda2 = lda2;
        j.ko0 = ko0; j.ko1 = ko1; j.ko2 = ko2;
        j.nStages = nStages; j.nBlocks = nBlocks; j.M = M;
        j.b0 = b0; j.b1 = b1; j.Yf = yf; j.Yh = yh; j.Yl = yl; j.relu = relu;
        return j;
    };

    // 1: weight prep
    prep_w_kernel<<<14, 256>>>(lin_p_w, lin_a_w, Wl, Wr, lin_w, wih, wil);
    // 2: input split
    prep_x_kernel<<<4096, 256>>>(x_paper, x_author, xph, xpl, xah, xal);
    // 3: zero all 3 histogram arrays
    zero3_kernel<<<256, 256>>>(cnt1, cnt2, cnt3);
    // 4: combined projection GEMM (paper K=256, relu + author K=128, relu)
    {
        Job jp = mkjob(xph, xpl, 256, 0,   wih + 0 * IMG, wil + 0 * IMG,
                       xph, xpl, 256, 128, wih + 1 * IMG, wil + 1 * IMG,
                       nullptr, nullptr, 0, 0, nullptr, nullptr,
                       2, GP, NPAPER, lin_p_b, nullptr, nullptr, yph0, ypl0, 1);
        Job ja = mkjob(xah, xal, 128, 0, wih + 2 * IMG, wil + 2 * IMG,
                       nullptr, nullptr, 0, 0, nullptr, nullptr,
                       nullptr, nullptr, 0, 0, nullptr, nullptr,
                       1, GA, NAUTHOR, lin_a_b, nullptr, nullptr, yah0, yal0, 1);
        gemm_bf<128><<<GP + GA, 512, S128>>>(jp, ja);
    }
    // 5-9: batched CSR build
    hist3_kernel<<<(3 * NEDGE + 255) / 256, 256>>>(a2p_dst, p2a_dst, p2p_dst, cnt1, cnt2, cnt3);
    scanb3_kernel<<<NBall, 1024>>>(cnt1, cnt2, cnt3, rp1, rp2, rp3, bsums);
    scanp3_kernel<<<3, 256>>>(bsums);
    scana3_kernel<<<NBall, 1024>>>(rp1, rp2, rp3, cnt1, cnt2, cnt3, bsums);
    fill3_kernel<<<(3 * NEDGE + 255) / 256, 256>>>(a2p_src, a2p_dst, cnt1, c1,
                                                   p2a_src, p2a_dst, cnt2, c2,
                                                   p2p_src, p2p_dst, cnt3, c3);

    ushortT *ypch = yph0, *ypcl = ypl0, *ypnh = yph1, *ypnl = ypl1;
    ushortT *yach = yah0, *yacl = yal0, *yanh = yah1, *yanl = yal1;
    const int GG = ((2 * NPAPER + NAUTHOR) * 32 + 255) / 256;

    for (int l = 0; l < 2; l++) {
        gather3_kernel<<<GG, 256>>>((const uint2*)yach, (const uint2*)yacl,
                                    (const uint2*)ypch, (const uint2*)ypcl,
                                    rp1, c1, (uint2*)mp1h, (uint2*)mp1l,
                                    rp3, c3, (uint2*)mp2h, (uint2*)mp2l,
                                    rp2, c2, (uint2*)mah,  (uint2*)mal);

        // combined layer GEMM: paper update (3 stages) + author update (2 stages)
        Job jp = mkjob(mp1h, mp1l, 128, 0, wih + (3 + l * 3 + 0) * IMG, wil + (3 + l * 3 + 0) * IMG,
                       mp2h, mp2l, 128, 0, wih + (3 + l * 3 + 2) * IMG, wil + (3 + l * 3 + 2) * IMG,
                       ypch, ypcl, 128, 0, wih + (9 + l) * IMG,          wil + (9 + l) * IMG,
                       3, GP, NPAPER,
                       bl + (size_t)(l * 3 + 0) * HD, bl + (size_t)(l * 3 + 2) * HD,
                       nullptr, ypnh, ypnl, 0);
        Job ja = mkjob(mah,  mal,  128, 0, wih + (3 + l * 3 + 1) * IMG, wil + (3 + l * 3 + 1) * IMG,
                       yach, yacl, 128, 0, wih + (11 + l) * IMG,         wil + (11 + l) * IMG,
                       nullptr, nullptr, 0, 0, nullptr, nullptr,
                       2, GA, NAUTHOR,
                       bl + (size_t)(l * 3 + 1) * HD, nullptr,
                       nullptr, yanh, yanl, 0);
        gemm_bf<128><<<GP + GA, 512, S128>>>(jp, ja);

        ushortT* u;
        u = ypch; ypch = ypnh; ypnh = u;
        u = ypcl; ypcl = ypnl; ypnl = u;
        u = yach; yach = yanh; yanh = u;
        u = yacl; yacl = yanl; yanl = u;
    }

    // final classifier (N=64), f32 output
    {
        Job jc = mkjob(ypch, ypcl, 128, 0, wih + 13 * IMG, wil + 13 * IMG,
                       nullptr, nullptr, 0, 0, nullptr, nullptr,
                       nullptr, nullptr, 0, 0, nullptr, nullptr,
                       1, GP, NPAPER, lin_b, nullptr, out, nullptr, nullptr, 0);
        gemm_bf<64><<<GP, 512, S64>>>(jc, jc);
    }
}